// round 13
// baseline (speedup 1.0000x reference)
#include <cuda_runtime.h>
#include <math.h>

#define Bt 8
#define Nt 2048
#define Dt 128
#define DP2 64             // bf16 pairs per row (Dt/2)
#define BN 16384           // Bt*Nt
#define CAP 96             // max in/out degree capacity (mean ~20.5, sigma ~4.5)

typedef unsigned long long ull;
typedef unsigned int uint;

// ---------------- scratch (static device allocations, allowed) ----------------
__device__ int   d_csc_cnt[BN];
__device__ int   d_csr_cnt[BN];
__device__ int   d_csc_idx[BN * CAP];
__device__ int   d_csr_idx[BN * CAP];
__device__ float d_h1   [BN * Dt];
__device__ float d_a1   [BN * Dt];
__device__ float d_hemb [BN * Dt];
__device__ float d_S    [BN * Dt];
__device__ float d_adjS [BN * Dt];
__device__ float d_StS  [Bt * Dt * Dt];
// bf16x2 split planes: uint2 per element-pair {hi(2xbf16), lo(2xbf16)}
__device__ uint2 d_x2   [BN * DP2];
__device__ uint2 d_agg2 [BN * DP2];
__device__ uint2 d_agg2a[BN * DP2];
__device__ uint2 d_h1s  [BN * DP2];
__device__ uint2 d_a1s  [BN * DP2];
__device__ uint2 d_Ws[4][2 * Dt * DP2];  // per layer: Wl rows 0..127, Wr rows 128..255
__device__ double d_E, d_F, d_nnz, d_ent;

// split two consecutive floats into {hi bf16x2, lo bf16x2}; element0 in low half
__device__ __forceinline__ uint2 split_bf16x2(float v0, float v1) {
    uint hi, lo;
    asm("cvt.rn.bf16x2.f32 %0, %1, %2;" : "=r"(hi) : "f"(v1), "f"(v0));
    float h0 = __uint_as_float(hi << 16);
    float h1 = __uint_as_float(hi & 0xFFFF0000u);
    float r0 = v0 - h0, r1 = v1 - h1;
    asm("cvt.rn.bf16x2.f32 %0, %1, %2;" : "=r"(lo) : "f"(r1), "f"(r0));
    return make_uint2(hi, lo);
}

// ---------------- kernels ----------------

__global__ void k_clear(float* out, int osz) {
    int stride = gridDim.x * blockDim.x;
    int i0 = blockIdx.x * blockDim.x + threadIdx.x;
    for (int i = i0; i < BN; i += stride) { d_csc_cnt[i] = 0; d_csr_cnt[i] = 0; }
    for (int i = i0; i < Bt * Dt * Dt; i += stride) d_StS[i] = 0.f;
    for (int i = i0; i < osz; i += stride) out[i] = 0.f;
    if (i0 == 0) { d_E = 0.0; d_F = 0.0; d_nnz = 0.0; d_ent = 0.0; }
}

// ONE launch: blocks [0,2048) split x; blocks [2048,2176) split the 4 weight pairs
__global__ void k_split_all(const float* __restrict__ x, uint2* __restrict__ x2,
                            const float* __restrict__ W0l, const float* __restrict__ W0r,
                            const float* __restrict__ W1l, const float* __restrict__ W1r,
                            const float* __restrict__ W2l, const float* __restrict__ W2r,
                            const float* __restrict__ W3l, const float* __restrict__ W3r) {
    if (blockIdx.x < 2048) {
        int i = blockIdx.x * blockDim.x + threadIdx.x;   // float4 index
        float4 v = *(const float4*)(x + i * 4);
        uint2 s[2] = {split_bf16x2(v.x, v.y), split_bf16x2(v.z, v.w)};
        *(uint4*)(x2 + i * 2) = *(uint4*)&s[0];
    } else {
        int wb = blockIdx.x - 2048;
        int layer = wb >> 5;
        int i = (wb & 31) * blockDim.x + threadIdx.x;    // 0 .. 2*Dt*Dt/4-1
        const float* Wl = (layer == 0) ? W0l : (layer == 1) ? W1l : (layer == 2) ? W2l : W3l;
        const float* Wr = (layer == 0) ? W0r : (layer == 1) ? W1r : (layer == 2) ? W2r : W3r;
        const float* src = (i < Dt * Dt / 4) ? Wl : Wr;
        int off = (i < Dt * Dt / 4) ? i * 4 : (i * 4 - Dt * Dt);
        float4 v = *(const float4*)(src + off);
        uint2 s[2] = {split_bf16x2(v.x, v.y), split_bf16x2(v.z, v.w)};
        *(uint4*)(d_Ws[layer] + i * 2) = *(uint4*)&s[0];
    }
}

// one block per adjacency row (b,i); builds CSC (in-edges per target) and CSR
// (out-edges per source). Also accumulates nnz (block-reduced, fire-and-forget RED).
__global__ void k_build(const float* __restrict__ adj) {
    __shared__ int bcnt[8];
    int row = blockIdx.x;                 // flat b*Nt + i
    int base = row & ~(Nt - 1);           // b*Nt
    const float4* ar = (const float4*)(adj + (size_t)row * Nt);
    int loc = 0;
    for (int j4 = threadIdx.x; j4 < Nt / 4; j4 += blockDim.x) {
        float4 v = ar[j4];
        int j = j4 << 2;
#pragma unroll
        for (int u = 0; u < 4; u++) {
            float f = (u == 0) ? v.x : (u == 1) ? v.y : (u == 2) ? v.z : v.w;
            if (f != 0.0f) {
                int t = base + j + u;
                int p = atomicAdd(&d_csc_cnt[t], 1);
                if (p < CAP) d_csc_idx[t * CAP + p] = row;
                int q = atomicAdd(&d_csr_cnt[row], 1);
                if (q < CAP) d_csr_idx[row * CAP + q] = t;
                loc++;
            }
        }
    }
#pragma unroll
    for (int off = 16; off; off >>= 1) loc += __shfl_xor_sync(~0u, loc, off);
    int wid = threadIdx.x >> 5, lane = threadIdx.x & 31;
    if (lane == 0) bcnt[wid] = loc;
    __syncthreads();
    if (threadIdx.x == 0) {
        int t = 0;
        for (int w = 0; w < 8; w++) t += bcnt[w];
        atomicAdd(&d_nnz, (double)t);     // no return use -> RED
    }
}

// warp per output row: CSC mean-gather of X, writes bf16x2 split form
__global__ void k_spmm(const float* __restrict__ X, float* __restrict__ outf,
                       uint2* __restrict__ out2, int use_csr, int scale) {
    int warp = (blockIdx.x * blockDim.x + threadIdx.x) >> 5;
    int lane = threadIdx.x & 31;
    if (warp >= BN) return;
    const int* cntp = use_csr ? d_csr_cnt : d_csc_cnt;
    const int* idxp = use_csr ? d_csr_idx : d_csc_idx;
    int c = cntp[warp];
    int cl = c < CAP ? c : CAP;
    const int* ip = idxp + warp * CAP;
    float4 acc = make_float4(0.f, 0.f, 0.f, 0.f);
    int e = 0;
    for (; e + 4 <= cl; e += 4) {
        int s0 = ip[e], s1 = ip[e + 1], s2 = ip[e + 2], s3 = ip[e + 3];
        float4 v0 = *(const float4*)(X + (size_t)s0 * Dt + (lane << 2));
        float4 v1 = *(const float4*)(X + (size_t)s1 * Dt + (lane << 2));
        float4 v2 = *(const float4*)(X + (size_t)s2 * Dt + (lane << 2));
        float4 v3 = *(const float4*)(X + (size_t)s3 * Dt + (lane << 2));
        acc.x += (v0.x + v1.x) + (v2.x + v3.x);
        acc.y += (v0.y + v1.y) + (v2.y + v3.y);
        acc.z += (v0.z + v1.z) + (v2.z + v3.z);
        acc.w += (v0.w + v1.w) + (v2.w + v3.w);
    }
    for (; e < cl; e++) {
        int s = ip[e];
        float4 v = *(const float4*)(X + (size_t)s * Dt + (lane << 2));
        acc.x += v.x; acc.y += v.y; acc.z += v.z; acc.w += v.w;
    }
    if (scale) {
        float sc = 1.0f / (float)(c > 1 ? c : 1);
        acc.x *= sc; acc.y *= sc; acc.z *= sc; acc.w *= sc;
    }
    if (outf)
        *(float4*)(outf + (size_t)warp * Dt + (lane << 2)) = acc;
    if (out2) {
        uint2 s[2] = {split_bf16x2(acc.x, acc.y), split_bf16x2(acc.z, acc.w)};
        *(uint4*)(out2 + (size_t)warp * DP2 + (lane << 1)) = *(uint4*)&s[0];
    }
}

// warp per row: dual CSC mean-gather of H and A in one pass (shared index list)
__global__ void k_spmm_dual(const float* __restrict__ H, const float* __restrict__ A,
                            uint2* __restrict__ outH, uint2* __restrict__ outA) {
    int warp = (blockIdx.x * blockDim.x + threadIdx.x) >> 5;
    int lane = threadIdx.x & 31;
    if (warp >= BN) return;
    int c = d_csc_cnt[warp];
    int cl = c < CAP ? c : CAP;
    const int* ip = d_csc_idx + warp * CAP;
    float4 ah = make_float4(0.f, 0.f, 0.f, 0.f);
    float4 aa = make_float4(0.f, 0.f, 0.f, 0.f);
    int e = 0;
    for (; e + 4 <= cl; e += 4) {
        int s0 = ip[e], s1 = ip[e + 1], s2 = ip[e + 2], s3 = ip[e + 3];
        float4 h0 = *(const float4*)(H + (size_t)s0 * Dt + (lane << 2));
        float4 h1 = *(const float4*)(H + (size_t)s1 * Dt + (lane << 2));
        float4 h2 = *(const float4*)(H + (size_t)s2 * Dt + (lane << 2));
        float4 h3 = *(const float4*)(H + (size_t)s3 * Dt + (lane << 2));
        float4 a0 = *(const float4*)(A + (size_t)s0 * Dt + (lane << 2));
        float4 a1 = *(const float4*)(A + (size_t)s1 * Dt + (lane << 2));
        float4 a2 = *(const float4*)(A + (size_t)s2 * Dt + (lane << 2));
        float4 a3 = *(const float4*)(A + (size_t)s3 * Dt + (lane << 2));
        ah.x += (h0.x + h1.x) + (h2.x + h3.x);
        ah.y += (h0.y + h1.y) + (h2.y + h3.y);
        ah.z += (h0.z + h1.z) + (h2.z + h3.z);
        ah.w += (h0.w + h1.w) + (h2.w + h3.w);
        aa.x += (a0.x + a1.x) + (a2.x + a3.x);
        aa.y += (a0.y + a1.y) + (a2.y + a3.y);
        aa.z += (a0.z + a1.z) + (a2.z + a3.z);
        aa.w += (a0.w + a1.w) + (a2.w + a3.w);
    }
    for (; e < cl; e++) {
        int s = ip[e];
        float4 h0 = *(const float4*)(H + (size_t)s * Dt + (lane << 2));
        float4 a0 = *(const float4*)(A + (size_t)s * Dt + (lane << 2));
        ah.x += h0.x; ah.y += h0.y; ah.z += h0.z; ah.w += h0.w;
        aa.x += a0.x; aa.y += a0.y; aa.z += a0.z; aa.w += a0.w;
    }
    float sc = 1.0f / (float)(c > 1 ? c : 1);
    ah.x *= sc; ah.y *= sc; ah.z *= sc; ah.w *= sc;
    aa.x *= sc; aa.y *= sc; aa.z *= sc; aa.w *= sc;
    uint2 sh[2] = {split_bf16x2(ah.x, ah.y), split_bf16x2(ah.z, ah.w)};
    uint2 sa[2] = {split_bf16x2(aa.x, aa.y), split_bf16x2(aa.z, aa.w)};
    *(uint4*)(outH + (size_t)warp * DP2 + (lane << 1)) = *(uint4*)&sh[0];
    *(uint4*)(outA + (size_t)warp * DP2 + (lane << 1)) = *(uint4*)&sa[0];
}

// ---------------------------------------------------------------------------
// fused dual-GEMM via bf16x2 tensor cores (3-MMA split) on PRE-SPLIT inputs,
// grid-packed: blockIdx.y in {0,1} selects one of two independent problems.
//   out = l2norm(relu(agg @ Wl^T + b + xin @ Wr^T))    [+ optional softmax+ent]
// Block: 64 rows x 128 cols, 256 threads = 8 warps (2M x 4N), warp 32x32.
// mma.m16n8k16 bf16, acc += Ah*Bh + Ah*Bl + Al*Bh.
// A frag (k-pair units): a0=(g,p) a1=(g+8,p) a2=(g,p+4) a3=(g+8,p+4)
// ---------------------------------------------------------------------------
#define KSTR 20
#define MMA_BF16(ac, a0, a1, a2, a3, b0, b1) \
    asm volatile("mma.sync.aligned.m16n8k16.row.col.f32.bf16.bf16.f32 " \
        "{%0,%1,%2,%3}, {%4,%5,%6,%7}, {%8,%9}, {%0,%1,%2,%3};" \
        : "+f"((ac)[0]), "+f"((ac)[1]), "+f"((ac)[2]), "+f"((ac)[3]) \
        : "r"(a0), "r"(a1), "r"(a2), "r"(a3), "r"(b0), "r"(b1))

__global__ void __launch_bounds__(256)
k_linear_pair(const uint2* __restrict__ Aa0, const uint2* __restrict__ Ab0,
              const uint2* __restrict__ W0, const float* __restrict__ b0,
              float* __restrict__ o0, uint2* __restrict__ o20,
              const uint2* __restrict__ Aa1, const uint2* __restrict__ Ab1,
              const uint2* __restrict__ W1, const float* __restrict__ b1,
              float* __restrict__ o1, uint2* __restrict__ o21,
              int softmax_y) {
    __shared__ uint2 As2[64 * KSTR];     // 10 KB
    __shared__ uint2 Bs2[128 * KSTR];    // 20 KB

    int y = blockIdx.y;
    const uint2* A2a = (y == 0) ? Aa0 : Aa1;
    const uint2* A2b = (y == 0) ? Ab0 : Ab1;
    const uint2* W2  = (y == 0) ? W0  : W1;
    const float* bias = (y == 0) ? b0 : b1;
    float* out  = (y == 0) ? o0  : o1;
    uint2* out2 = (y == 0) ? o20 : o21;
    int dosm = (y == softmax_y);

    int tx = threadIdx.x;
    int lane = tx & 31;
    int warp = tx >> 5;
    int warpM = warp >> 2;
    int warpN = warp & 3;
    int lq = lane >> 2;
    int lr = lane & 3;
    int r0 = blockIdx.x * 64;

    float acc[2][4][4];
#pragma unroll
    for (int mi = 0; mi < 2; mi++)
#pragma unroll
        for (int nj = 0; nj < 4; nj++)
#pragma unroll
            for (int q = 0; q < 4; q++) acc[mi][nj][q] = 0.f;

    for (int kc = 0; kc < 8; kc++) {            // 8 chunks of K=32 (16 pairs)
        const uint2* Asrc = (kc < 4) ? A2a : A2b;
        int wbase = (kc < 4) ? 0 : Dt * DP2;
        int kb = (kc & 3) * 16;                 // pair offset within row
#pragma unroll
        for (int it = 0; it < 2; it++) {
            int j = tx + it * 256;
            int row = j >> 3, kp = (j & 7) << 1;
            uint4 v = *(const uint4*)(Asrc + (size_t)(r0 + row) * DP2 + kb + kp);
            *(uint4*)&As2[row * KSTR + kp] = v;
        }
#pragma unroll
        for (int it = 0; it < 4; it++) {
            int j = tx + it * 256;
            int row = j >> 3, kp = (j & 7) << 1;
            uint4 v = *(const uint4*)(W2 + wbase + row * DP2 + kb + kp);
            *(uint4*)&Bs2[row * KSTR + kp] = v;
        }
        __syncthreads();
#pragma unroll
        for (int ks = 0; ks < 2; ks++) {        // 2 k16-steps per chunk
            int k0 = ks * 8;
            uint2 af[2][4];
#pragma unroll
            for (int mi = 0; mi < 2; mi++) {
                int row = warpM * 32 + mi * 16 + lq;
                af[mi][0] = As2[row * KSTR + k0 + lr];
                af[mi][1] = As2[(row + 8) * KSTR + k0 + lr];
                af[mi][2] = As2[row * KSTR + k0 + 4 + lr];
                af[mi][3] = As2[(row + 8) * KSTR + k0 + 4 + lr];
            }
            uint2 bf[4][2];
#pragma unroll
            for (int nj = 0; nj < 4; nj++) {
                int n = warpN * 32 + nj * 8 + lq;
                bf[nj][0] = Bs2[n * KSTR + k0 + lr];
                bf[nj][1] = Bs2[n * KSTR + k0 + 4 + lr];
            }
#pragma unroll
            for (int mi = 0; mi < 2; mi++)
#pragma unroll
                for (int nj = 0; nj < 4; nj++) {
                    MMA_BF16(acc[mi][nj],
                             af[mi][0].x, af[mi][1].x, af[mi][2].x, af[mi][3].x,
                             bf[nj][0].x, bf[nj][1].x);
                    MMA_BF16(acc[mi][nj],
                             af[mi][0].x, af[mi][1].x, af[mi][2].x, af[mi][3].x,
                             bf[nj][0].y, bf[nj][1].y);
                    MMA_BF16(acc[mi][nj],
                             af[mi][0].y, af[mi][1].y, af[mi][2].y, af[mi][3].y,
                             bf[nj][0].x, bf[nj][1].x);
                }
        }
        __syncthreads();
    }

    // ---- epilogue: bias + relu + row L2 norm (+ optional softmax/entropy) ----
    float* red = (float*)As2;             // [64][4]
    float* entbuf = red + 256;            // [8]
    float bv[4][2];
#pragma unroll
    for (int nj = 0; nj < 4; nj++) {
        int col = warpN * 32 + nj * 8 + 2 * lr;
        bv[nj][0] = bias[col];
        bv[nj][1] = bias[col + 1];
    }
    float ss[2][2];
#pragma unroll
    for (int mi = 0; mi < 2; mi++) { ss[mi][0] = 0.f; ss[mi][1] = 0.f; }
#pragma unroll
    for (int mi = 0; mi < 2; mi++)
#pragma unroll
        for (int nj = 0; nj < 4; nj++) {
            float v0 = fmaxf(acc[mi][nj][0] + bv[nj][0], 0.f);
            float v1 = fmaxf(acc[mi][nj][1] + bv[nj][1], 0.f);
            float v2 = fmaxf(acc[mi][nj][2] + bv[nj][0], 0.f);
            float v3 = fmaxf(acc[mi][nj][3] + bv[nj][1], 0.f);
            acc[mi][nj][0] = v0; acc[mi][nj][1] = v1;
            acc[mi][nj][2] = v2; acc[mi][nj][3] = v3;
            ss[mi][0] += v0 * v0 + v1 * v1;
            ss[mi][1] += v2 * v2 + v3 * v3;
        }
#pragma unroll
    for (int mi = 0; mi < 2; mi++)
#pragma unroll
        for (int h = 0; h < 2; h++) {
            float s = ss[mi][h];
            s += __shfl_xor_sync(~0u, s, 1);
            s += __shfl_xor_sync(~0u, s, 2);
            ss[mi][h] = s;
        }
    if (lr == 0) {
#pragma unroll
        for (int mi = 0; mi < 2; mi++)
#pragma unroll
            for (int h = 0; h < 2; h++) {
                int row = warpM * 32 + mi * 16 + lq + h * 8;
                red[row * 4 + warpN] = ss[mi][h];
            }
    }
    __syncthreads();
#pragma unroll
    for (int mi = 0; mi < 2; mi++) {
        int rowA = warpM * 32 + mi * 16 + lq;
        float t0 = red[rowA * 4] + red[rowA * 4 + 1] + red[rowA * 4 + 2] + red[rowA * 4 + 3];
        float t1 = red[(rowA + 8) * 4] + red[(rowA + 8) * 4 + 1] + red[(rowA + 8) * 4 + 2] + red[(rowA + 8) * 4 + 3];
        float inv0 = 1.0f / (sqrtf(t0) + 1e-9f);
        float inv1 = 1.0f / (sqrtf(t1) + 1e-9f);
#pragma unroll
        for (int nj = 0; nj < 4; nj++) {
            acc[mi][nj][0] *= inv0; acc[mi][nj][1] *= inv0;
            acc[mi][nj][2] *= inv1; acc[mi][nj][3] *= inv1;
        }
    }

    if (!dosm) {
#pragma unroll
        for (int mi = 0; mi < 2; mi++) {
            int rowA = warpM * 32 + mi * 16 + lq;
#pragma unroll
            for (int nj = 0; nj < 4; nj++) {
                int col = warpN * 32 + nj * 8 + 2 * lr;
                float2 o0v = make_float2(acc[mi][nj][0], acc[mi][nj][1]);
                float2 o1v = make_float2(acc[mi][nj][2], acc[mi][nj][3]);
                *(float2*)(out + (size_t)(r0 + rowA) * Dt + col) = o0v;
                *(float2*)(out + (size_t)(r0 + rowA + 8) * Dt + col) = o1v;
                if (out2) {
                    out2[(size_t)(r0 + rowA) * DP2 + (col >> 1)]     = split_bf16x2(o0v.x, o0v.y);
                    out2[(size_t)(r0 + rowA + 8) * DP2 + (col >> 1)] = split_bf16x2(o1v.x, o1v.y);
                }
            }
        }
        return;
    }

    // ---- softmax + entropy over each 128-wide row ----
    __syncthreads();                      // red reuse
    float mx[2][2];
#pragma unroll
    for (int mi = 0; mi < 2; mi++) {
        float m0 = -1e30f, m1 = -1e30f;
#pragma unroll
        for (int nj = 0; nj < 4; nj++) {
            m0 = fmaxf(m0, fmaxf(acc[mi][nj][0], acc[mi][nj][1]));
            m1 = fmaxf(m1, fmaxf(acc[mi][nj][2], acc[mi][nj][3]));
        }
        m0 = fmaxf(m0, __shfl_xor_sync(~0u, m0, 1));
        m0 = fmaxf(m0, __shfl_xor_sync(~0u, m0, 2));
        m1 = fmaxf(m1, __shfl_xor_sync(~0u, m1, 1));
        m1 = fmaxf(m1, __shfl_xor_sync(~0u, m1, 2));
        if (lr == 0) {
            int rowA = warpM * 32 + mi * 16 + lq;
            red[rowA * 4 + warpN] = m0;
            red[(rowA + 8) * 4 + warpN] = m1;
        }
    }
    __syncthreads();
#pragma unroll
    for (int mi = 0; mi < 2; mi++) {
        int rowA = warpM * 32 + mi * 16 + lq;
        mx[mi][0] = fmaxf(fmaxf(red[rowA * 4], red[rowA * 4 + 1]),
                          fmaxf(red[rowA * 4 + 2], red[rowA * 4 + 3]));
        mx[mi][1] = fmaxf(fmaxf(red[(rowA + 8) * 4], red[(rowA + 8) * 4 + 1]),
                          fmaxf(red[(rowA + 8) * 4 + 2], red[(rowA + 8) * 4 + 3]));
    }
    __syncthreads();
#pragma unroll
    for (int mi = 0; mi < 2; mi++) {
        float s0 = 0.f, s1 = 0.f;
#pragma unroll
        for (int nj = 0; nj < 4; nj++) {
            float e0 = expf(acc[mi][nj][0] - mx[mi][0]);
            float e1 = expf(acc[mi][nj][1] - mx[mi][0]);
            float e2 = expf(acc[mi][nj][2] - mx[mi][1]);
            float e3 = expf(acc[mi][nj][3] - mx[mi][1]);
            acc[mi][nj][0] = e0; acc[mi][nj][1] = e1;
            acc[mi][nj][2] = e2; acc[mi][nj][3] = e3;
            s0 += e0 + e1; s1 += e2 + e3;
        }
        s0 += __shfl_xor_sync(~0u, s0, 1);
        s0 += __shfl_xor_sync(~0u, s0, 2);
        s1 += __shfl_xor_sync(~0u, s1, 1);
        s1 += __shfl_xor_sync(~0u, s1, 2);
        if (lr == 0) {
            int rowA = warpM * 32 + mi * 16 + lq;
            red[rowA * 4 + warpN] = s0;
            red[(rowA + 8) * 4 + warpN] = s1;
        }
    }
    __syncthreads();
    float ent = 0.f;
#pragma unroll
    for (int mi = 0; mi < 2; mi++) {
        int rowA = warpM * 32 + mi * 16 + lq;
        float s0 = red[rowA * 4] + red[rowA * 4 + 1] + red[rowA * 4 + 2] + red[rowA * 4 + 3];
        float s1 = red[(rowA + 8) * 4] + red[(rowA + 8) * 4 + 1] + red[(rowA + 8) * 4 + 2] + red[(rowA + 8) * 4 + 3];
        float i0 = 1.0f / s0, i1 = 1.0f / s1;
#pragma unroll
        for (int nj = 0; nj < 4; nj++) {
            int col = warpN * 32 + nj * 8 + 2 * lr;
            float p0 = acc[mi][nj][0] * i0, p1 = acc[mi][nj][1] * i0;
            float p2 = acc[mi][nj][2] * i1, p3 = acc[mi][nj][3] * i1;
            ent -= p0 * logf(p0 + 1e-15f) + p1 * logf(p1 + 1e-15f)
                 + p2 * logf(p2 + 1e-15f) + p3 * logf(p3 + 1e-15f);
            *(float2*)(out + (size_t)(r0 + rowA) * Dt + col) = make_float2(p0, p1);
            *(float2*)(out + (size_t)(r0 + rowA + 8) * Dt + col) = make_float2(p2, p3);
        }
    }
#pragma unroll
    for (int off = 16; off; off >>= 1) ent += __shfl_xor_sync(~0u, ent, off);
    __syncthreads();
    if (lane == 0) entbuf[warp] = ent;
    __syncthreads();
    if (tx == 0) {
        float t = 0.f;
        for (int w = 0; w < 8; w++) t += entbuf[w];
        atomicAdd(&d_ent, (double)t);
    }
}

// warp per row r: adjS[r] = sum_{m in csr[r]} S[m]  AND  E += dot(S[r], adjS[r])
__global__ void k_adjS_E(const float* __restrict__ S, float* __restrict__ adjS) {
    __shared__ float esm[8];
    int warp_l = threadIdx.x >> 5;
    int warp = (blockIdx.x * blockDim.x + threadIdx.x) >> 5;
    int lane = threadIdx.x & 31;
    float loc = 0.f;
    if (warp < BN) {
        int c = d_csr_cnt[warp];
        int cl = c < CAP ? c : CAP;
        const int* ip = d_csr_idx + warp * CAP;
        float4 acc = make_float4(0.f, 0.f, 0.f, 0.f);
        int e = 0;
        for (; e + 4 <= cl; e += 4) {
            int s0 = ip[e], s1 = ip[e + 1], s2 = ip[e + 2], s3 = ip[e + 3];
            float4 v0 = *(const float4*)(S + (size_t)s0 * Dt + (lane << 2));
            float4 v1 = *(const float4*)(S + (size_t)s1 * Dt + (lane << 2));
            float4 v2 = *(const float4*)(S + (size_t)s2 * Dt + (lane << 2));
            float4 v3 = *(const float4*)(S + (size_t)s3 * Dt + (lane << 2));
            acc.x += (v0.x + v1.x) + (v2.x + v3.x);
            acc.y += (v0.y + v1.y) + (v2.y + v3.y);
            acc.z += (v0.z + v1.z) + (v2.z + v3.z);
            acc.w += (v0.w + v1.w) + (v2.w + v3.w);
        }
        for (; e < cl; e++) {
            int s = ip[e];
            float4 v = *(const float4*)(S + (size_t)s * Dt + (lane << 2));
            acc.x += v.x; acc.y += v.y; acc.z += v.z; acc.w += v.w;
        }
        *(float4*)(adjS + (size_t)warp * Dt + (lane << 2)) = acc;
        float4 sr = *(const float4*)(S + (size_t)warp * Dt + (lane << 2));
        loc = sr.x * acc.x + sr.y * acc.y + sr.z * acc.z + sr.w * acc.w;
#pragma unroll
        for (int off = 16; off; off >>= 1) loc += __shfl_xor_sync(~0u, loc, off);
    }
    if (lane == 0) esm[warp_l] = loc;
    __syncthreads();
    if (threadIdx.x == 0) {
        float t = 0.f;
        for (int w = 0; w < 8; w++) t += esm[w];
        atomicAdd(&d_E, (double)t);
    }
}

// three batched A^T@B products in one launch: z selects (A,B,C) operands.
// z==2 computes S^T S: B tile identical to A tile, so skip its staging.
#define AR 32
#define AI 4
__global__ void k_atb3(const float* __restrict__ S, const float* __restrict__ hemb,
                       const float* __restrict__ adjS, float* __restrict__ hP,
                       float* __restrict__ aP, float* __restrict__ StS) {
    __shared__ float As[AR][Dt];
    __shared__ float Bs[AR][Dt];
    int b = blockIdx.y;
    int z = blockIdx.z;
    const float* A  = S;
    const float* Bm = (z == 0) ? hemb : (z == 1) ? adjS : S;
    float* C        = (z == 0) ? hP   : (z == 1) ? aP   : StS;
    float (*Bsel)[Dt] = (z == 2) ? As : Bs;
    ull acc[8][4];
#pragma unroll
    for (int i = 0; i < 8; i++)
#pragma unroll
        for (int j = 0; j < 4; j++) acc[i][j] = 0ull;
    int tk = threadIdx.x >> 4, td = threadIdx.x & 15;
    for (int c = 0; c < AI; c++) {
        int n0 = (blockIdx.x * AI + c) * AR;
        const float* Ap = A  + ((size_t)b * Nt + n0) * Dt;
        const float* Bp = Bm + ((size_t)b * Nt + n0) * Dt;
        __syncthreads();
        for (int t = threadIdx.x; t < AR * 32; t += 256) {
            int r = t >> 5, k4 = (t & 31) << 2;
            *(float4*)&As[r][k4] = *(const float4*)(Ap + r * Dt + k4);
            if (z != 2)
                *(float4*)&Bs[r][k4] = *(const float4*)(Bp + r * Dt + k4);
        }
        __syncthreads();
        for (int n = 0; n < AR; n++) {
            float a[8];
            *(float4*)&a[0] = *(const float4*)&As[n][tk * 8];
            *(float4*)&a[4] = *(const float4*)&As[n][tk * 8 + 4];
            const ulonglong2* bp = (const ulonglong2*)&Bsel[n][td * 8];
            ulonglong2 b01 = bp[0];
            ulonglong2 b23 = bp[1];
            ull ad[8];
#pragma unroll
            for (int i = 0; i < 8; i++) {
                unsigned int ab = __float_as_uint(a[i]);
                asm("mov.b64 %0, {%1, %1};" : "=l"(ad[i]) : "r"(ab));
            }
#pragma unroll
            for (int i = 0; i < 8; i++) {
                asm("fma.rn.f32x2 %0, %1, %2, %0;" : "+l"(acc[i][0]) : "l"(ad[i]), "l"(b01.x));
                asm("fma.rn.f32x2 %0, %1, %2, %0;" : "+l"(acc[i][1]) : "l"(ad[i]), "l"(b01.y));
                asm("fma.rn.f32x2 %0, %1, %2, %0;" : "+l"(acc[i][2]) : "l"(ad[i]), "l"(b23.x));
                asm("fma.rn.f32x2 %0, %1, %2, %0;" : "+l"(acc[i][3]) : "l"(ad[i]), "l"(b23.y));
            }
        }
    }
    size_t cb = (size_t)b * Dt * Dt;
#pragma unroll
    for (int i = 0; i < 8; i++)
#pragma unroll
        for (int j = 0; j < 4; j++) {
            float lo, hi;
            asm("mov.b64 {%0, %1}, %2;" : "=f"(lo), "=f"(hi) : "l"(acc[i][j]));
            atomicAdd(&C[cb + (size_t)(tk * 8 + i) * Dt + (td * 8 + 2 * j)], lo);
            atomicAdd(&C[cb + (size_t)(tk * 8 + i) * Dt + (td * 8 + 2 * j + 1)], hi);
        }
}

__global__ void k_sumsq() {
    __shared__ float sm[8];
    int i = blockIdx.x * blockDim.x + threadIdx.x;
    float x = (i < Bt * Dt * Dt) ? d_StS[i] : 0.f;
    float v = x * x;
#pragma unroll
    for (int off = 16; off; off >>= 1) v += __shfl_xor_sync(~0u, v, off);
    int wid = threadIdx.x >> 5, lane = threadIdx.x & 31;
    if (lane == 0) sm[wid] = v;
    __syncthreads();
    if (threadIdx.x == 0) {
        float t = 0.f;
        for (int w = 0; w < 8; w++) t += sm[w];
        atomicAdd(&d_F, (double)t);
    }
}

__global__ void k_final(float* out) {
    double l2 = d_nnz - 2.0 * d_E + d_F;
    if (l2 < 0.0) l2 = 0.0;
    out[2 * Bt * Dt * Dt]     = (float)(sqrt(l2) / ((double)Bt * Nt * Nt));
    out[2 * Bt * Dt * Dt + 1] = (float)(d_ent / (double)BN);
}

// ---------------- launch ----------------

extern "C" void kernel_launch(void* const* d_in, const int* in_sizes, int n_in,
                              void* d_out, int out_size) {
    const float* x    = (const float*)d_in[0];
    const float* adj  = (const float*)d_in[1];
    const float* We1l = (const float*)d_in[2];
    const float* be1  = (const float*)d_in[3];
    const float* We1r = (const float*)d_in[4];
    const float* We2l = (const float*)d_in[5];
    const float* be2  = (const float*)d_in[6];
    const float* We2r = (const float*)d_in[7];
    const float* Wa1l = (const float*)d_in[8];
    const float* ba1  = (const float*)d_in[9];
    const float* Wa1r = (const float*)d_in[10];
    const float* Wa2l = (const float*)d_in[11];
    const float* ba2  = (const float*)d_in[12];
    const float* Wa2r = (const float*)d_in[13];
    float* out = (float*)d_out;

    void* p;
    cudaGetSymbolAddress(&p, d_h1);    float* h1    = (float*)p;
    cudaGetSymbolAddress(&p, d_a1);    float* a1    = (float*)p;
    cudaGetSymbolAddress(&p, d_hemb);  float* hemb  = (float*)p;
    cudaGetSymbolAddress(&p, d_S);     float* S     = (float*)p;
    cudaGetSymbolAddress(&p, d_adjS);  float* adjS  = (float*)p;
    cudaGetSymbolAddress(&p, d_StS);   float* StS   = (float*)p;
    cudaGetSymbolAddress(&p, d_x2);    uint2* x2    = (uint2*)p;
    cudaGetSymbolAddress(&p, d_agg2);  uint2* agg2  = (uint2*)p;
    cudaGetSymbolAddress(&p, d_agg2a); uint2* agg2a = (uint2*)p;
    cudaGetSymbolAddress(&p, d_h1s);   uint2* h1s   = (uint2*)p;
    cudaGetSymbolAddress(&p, d_a1s);   uint2* a1s   = (uint2*)p;
    cudaGetSymbolAddress(&p, d_Ws);    uint2* Ws    = (uint2*)p;
    const int WSZ = 2 * Dt * DP2;

    k_clear<<<256, 256>>>(out, out_size);
    k_build<<<BN, 256>>>(adj);

    // one-time splits (x + all 4 weight pairs, one grid-packed launch)
    k_split_all<<<2048 + 128, 256>>>(x, x2, We1l, We1r, Wa1l, Wa1r,
                                     We2l, We2r, Wa2l, Wa2r);

    // agg1 = adj^T x / deg  (shared by emb1 and assign1), split form
    k_spmm<<<BN / 8, 256>>>(x, nullptr, agg2, 0, 1);

    // layer-1: both linears grid-packed into one launch
    k_linear_pair<<<dim3(BN / 64, 2), 256>>>(
        agg2, x2, Ws + 0 * WSZ, be1, h1, h1s,
        agg2, x2, Ws + 1 * WSZ, ba1, a1, a1s, -1);

    // layer-2 gathers fused (shared CSC index reads)
    k_spmm_dual<<<BN / 8, 256>>>(h1, a1, agg2, agg2a);

    // layer-2: both linears grid-packed; y=1 (assign) fuses softmax+entropy
    k_linear_pair<<<dim3(BN / 64, 2), 256>>>(
        agg2,  h1s, Ws + 2 * WSZ, be2, hemb, nullptr,
        agg2a, a1s, Ws + 3 * WSZ, ba2, S, nullptr, 1);

    // adjS = adj @ S (CSR gather) fused with E = sum_n dot(S[n], adjS[n])
    k_adjS_E<<<BN / 8, 256>>>(S, adjS);

    // three pooled products in ONE launch (384 blocks, fills the chip)
    k_atb3<<<dim3(Nt / (AR * AI), Bt, 3), 256>>>(S, hemb, adjS, out, out + Bt * Dt * Dt, StS);

    k_sumsq<<<(Bt * Dt * Dt) / 256, 256>>>();
    k_final<<<1, 1>>>(out);
}

// round 14
// speedup vs baseline: 1.0339x; 1.0339x over previous
#include <cuda_runtime.h>
#include <math.h>

#define Bt 8
#define Nt 2048
#define Dt 128
#define DP2 64             // bf16 pairs per row (Dt/2)
#define BN 16384           // Bt*Nt
#define CAP 96             // max in/out degree capacity (mean ~20.5, sigma ~4.5)

typedef unsigned long long ull;
typedef unsigned int uint;

// ---------------- scratch (static device allocations, allowed) ----------------
__device__ int   d_csc_cnt[BN];
__device__ int   d_csr_cnt[BN];
__device__ int   d_csc_idx[BN * CAP];
__device__ int   d_csr_idx[BN * CAP];
__device__ float d_h1   [BN * Dt];
__device__ float d_a1   [BN * Dt];
__device__ float d_hemb [BN * Dt];
__device__ float d_S    [BN * Dt];
__device__ float d_adjS [BN * Dt];
__device__ float d_StS  [Bt * Dt * Dt];
// bf16x2 split planes: uint2 per element-pair {hi(2xbf16), lo(2xbf16)}
__device__ uint2 d_x2   [BN * DP2];
__device__ uint2 d_agg2 [BN * DP2];
__device__ uint2 d_agg2a[BN * DP2];
__device__ uint2 d_h1s  [BN * DP2];
__device__ uint2 d_a1s  [BN * DP2];
__device__ uint2 d_Ws[4][2 * Dt * DP2];  // per layer: Wl rows 0..127, Wr rows 128..255
__device__ double d_E, d_F, d_nnz, d_ent;

// split two consecutive floats into {hi bf16x2, lo bf16x2}; element0 in low half
__device__ __forceinline__ uint2 split_bf16x2(float v0, float v1) {
    uint hi, lo;
    asm("cvt.rn.bf16x2.f32 %0, %1, %2;" : "=r"(hi) : "f"(v1), "f"(v0));
    float h0 = __uint_as_float(hi << 16);
    float h1 = __uint_as_float(hi & 0xFFFF0000u);
    float r0 = v0 - h0, r1 = v1 - h1;
    asm("cvt.rn.bf16x2.f32 %0, %1, %2;" : "=r"(lo) : "f"(r1), "f"(r0));
    return make_uint2(hi, lo);
}

// ---------------- kernels ----------------

__global__ void k_clear(float* out, int osz) {
    int stride = gridDim.x * blockDim.x;
    int i0 = blockIdx.x * blockDim.x + threadIdx.x;
    for (int i = i0; i < BN; i += stride) { d_csc_cnt[i] = 0; d_csr_cnt[i] = 0; }
    for (int i = i0; i < Bt * Dt * Dt; i += stride) d_StS[i] = 0.f;
    for (int i = i0; i < osz; i += stride) out[i] = 0.f;
    if (i0 == 0) { d_E = 0.0; d_F = 0.0; d_nnz = 0.0; d_ent = 0.0; }
}

// ONE launch, grid-packed independent work:
//   blocks [0, BN)            : build CSC/CSR from adjacency row
//   blocks [BN, BN+2048)      : split x into bf16x2 planes
//   blocks [BN+2048, BN+2176) : split the 4 weight pairs
__global__ void k_build_split(const float* __restrict__ adj,
                              const float* __restrict__ x, uint2* __restrict__ x2,
                              const float* __restrict__ W0l, const float* __restrict__ W0r,
                              const float* __restrict__ W1l, const float* __restrict__ W1r,
                              const float* __restrict__ W2l, const float* __restrict__ W2r,
                              const float* __restrict__ W3l, const float* __restrict__ W3r) {
    if (blockIdx.x < BN) {
        int row = blockIdx.x;                 // flat b*Nt + i
        int base = row & ~(Nt - 1);           // b*Nt
        const float4* ar = (const float4*)(adj + (size_t)row * Nt);
        for (int j4 = threadIdx.x; j4 < Nt / 4; j4 += blockDim.x) {
            float4 v = ar[j4];
            int j = j4 << 2;
#pragma unroll
            for (int u = 0; u < 4; u++) {
                float f = (u == 0) ? v.x : (u == 1) ? v.y : (u == 2) ? v.z : v.w;
                if (f != 0.0f) {
                    int t = base + j + u;
                    int p = atomicAdd(&d_csc_cnt[t], 1);
                    if (p < CAP) d_csc_idx[t * CAP + p] = row;
                    int q = atomicAdd(&d_csr_cnt[row], 1);
                    if (q < CAP) d_csr_idx[row * CAP + q] = t;
                }
            }
        }
    } else if (blockIdx.x < BN + 2048) {
        int i = (blockIdx.x - BN) * blockDim.x + threadIdx.x;   // float4 index
        float4 v = *(const float4*)(x + i * 4);
        uint2 s[2] = {split_bf16x2(v.x, v.y), split_bf16x2(v.z, v.w)};
        *(uint4*)(x2 + i * 2) = *(uint4*)&s[0];
    } else {
        int wb = blockIdx.x - BN - 2048;
        int layer = wb >> 5;
        int i = (wb & 31) * blockDim.x + threadIdx.x;           // 0 .. 2*Dt*Dt/4-1
        const float* Wl = (layer == 0) ? W0l : (layer == 1) ? W1l : (layer == 2) ? W2l : W3l;
        const float* Wr = (layer == 0) ? W0r : (layer == 1) ? W1r : (layer == 2) ? W2r : W3r;
        const float* src = (i < Dt * Dt / 4) ? Wl : Wr;
        int off = (i < Dt * Dt / 4) ? i * 4 : (i * 4 - Dt * Dt);
        float4 v = *(const float4*)(src + off);
        uint2 s[2] = {split_bf16x2(v.x, v.y), split_bf16x2(v.z, v.w)};
        *(uint4*)(d_Ws[layer] + i * 2) = *(uint4*)&s[0];
    }
}

// warp per output row: CSC mean-gather of X, writes bf16x2 split form
__global__ void k_spmm(const float* __restrict__ X, float* __restrict__ outf,
                       uint2* __restrict__ out2, int use_csr, int scale) {
    int warp = (blockIdx.x * blockDim.x + threadIdx.x) >> 5;
    int lane = threadIdx.x & 31;
    if (warp >= BN) return;
    const int* cntp = use_csr ? d_csr_cnt : d_csc_cnt;
    const int* idxp = use_csr ? d_csr_idx : d_csc_idx;
    int c = cntp[warp];
    int cl = c < CAP ? c : CAP;
    const int* ip = idxp + warp * CAP;
    float4 acc = make_float4(0.f, 0.f, 0.f, 0.f);
    int e = 0;
    for (; e + 4 <= cl; e += 4) {
        int s0 = ip[e], s1 = ip[e + 1], s2 = ip[e + 2], s3 = ip[e + 3];
        float4 v0 = *(const float4*)(X + (size_t)s0 * Dt + (lane << 2));
        float4 v1 = *(const float4*)(X + (size_t)s1 * Dt + (lane << 2));
        float4 v2 = *(const float4*)(X + (size_t)s2 * Dt + (lane << 2));
        float4 v3 = *(const float4*)(X + (size_t)s3 * Dt + (lane << 2));
        acc.x += (v0.x + v1.x) + (v2.x + v3.x);
        acc.y += (v0.y + v1.y) + (v2.y + v3.y);
        acc.z += (v0.z + v1.z) + (v2.z + v3.z);
        acc.w += (v0.w + v1.w) + (v2.w + v3.w);
    }
    for (; e < cl; e++) {
        int s = ip[e];
        float4 v = *(const float4*)(X + (size_t)s * Dt + (lane << 2));
        acc.x += v.x; acc.y += v.y; acc.z += v.z; acc.w += v.w;
    }
    if (scale) {
        float sc = 1.0f / (float)(c > 1 ? c : 1);
        acc.x *= sc; acc.y *= sc; acc.z *= sc; acc.w *= sc;
    }
    if (outf)
        *(float4*)(outf + (size_t)warp * Dt + (lane << 2)) = acc;
    if (out2) {
        uint2 s[2] = {split_bf16x2(acc.x, acc.y), split_bf16x2(acc.z, acc.w)};
        *(uint4*)(out2 + (size_t)warp * DP2 + (lane << 1)) = *(uint4*)&s[0];
    }
}

// warp per row: dual CSC mean-gather of H and A in one pass (shared index list)
__global__ void k_spmm_dual(const float* __restrict__ H, const float* __restrict__ A,
                            uint2* __restrict__ outH, uint2* __restrict__ outA) {
    int warp = (blockIdx.x * blockDim.x + threadIdx.x) >> 5;
    int lane = threadIdx.x & 31;
    if (warp >= BN) return;
    int c = d_csc_cnt[warp];
    int cl = c < CAP ? c : CAP;
    const int* ip = d_csc_idx + warp * CAP;
    float4 ah = make_float4(0.f, 0.f, 0.f, 0.f);
    float4 aa = make_float4(0.f, 0.f, 0.f, 0.f);
    int e = 0;
    for (; e + 2 <= cl; e += 2) {
        int s0 = ip[e], s1 = ip[e + 1];
        float4 h0 = *(const float4*)(H + (size_t)s0 * Dt + (lane << 2));
        float4 a0 = *(const float4*)(A + (size_t)s0 * Dt + (lane << 2));
        float4 h1 = *(const float4*)(H + (size_t)s1 * Dt + (lane << 2));
        float4 a1 = *(const float4*)(A + (size_t)s1 * Dt + (lane << 2));
        ah.x += h0.x + h1.x; ah.y += h0.y + h1.y; ah.z += h0.z + h1.z; ah.w += h0.w + h1.w;
        aa.x += a0.x + a1.x; aa.y += a0.y + a1.y; aa.z += a0.z + a1.z; aa.w += a0.w + a1.w;
    }
    if (e < cl) {
        int s = ip[e];
        float4 h0 = *(const float4*)(H + (size_t)s * Dt + (lane << 2));
        float4 a0 = *(const float4*)(A + (size_t)s * Dt + (lane << 2));
        ah.x += h0.x; ah.y += h0.y; ah.z += h0.z; ah.w += h0.w;
        aa.x += a0.x; aa.y += a0.y; aa.z += a0.z; aa.w += a0.w;
    }
    float sc = 1.0f / (float)(c > 1 ? c : 1);
    ah.x *= sc; ah.y *= sc; ah.z *= sc; ah.w *= sc;
    aa.x *= sc; aa.y *= sc; aa.z *= sc; aa.w *= sc;
    uint2 sh[2] = {split_bf16x2(ah.x, ah.y), split_bf16x2(ah.z, ah.w)};
    uint2 sa[2] = {split_bf16x2(aa.x, aa.y), split_bf16x2(aa.z, aa.w)};
    *(uint4*)(outH + (size_t)warp * DP2 + (lane << 1)) = *(uint4*)&sh[0];
    *(uint4*)(outA + (size_t)warp * DP2 + (lane << 1)) = *(uint4*)&sa[0];
}

// ---------------------------------------------------------------------------
// fused dual-GEMM via bf16x2 tensor cores (3-MMA split) on PRE-SPLIT inputs,
// grid-packed: blockIdx.y in {0,1} selects one of two independent problems.
//   out = l2norm(relu(agg @ Wl^T + b + xin @ Wr^T))    [+ optional softmax+ent]
// Block: 64 rows x 128 cols, 256 threads = 8 warps (2M x 4N), warp 32x32.
// mma.m16n8k16 bf16, acc += Ah*Bh + Ah*Bl + Al*Bh.
// A frag (k-pair units): a0=(g,p) a1=(g+8,p) a2=(g,p+4) a3=(g+8,p+4)
// ---------------------------------------------------------------------------
#define KSTR 20
#define MMA_BF16(ac, a0, a1, a2, a3, b0, b1) \
    asm volatile("mma.sync.aligned.m16n8k16.row.col.f32.bf16.bf16.f32 " \
        "{%0,%1,%2,%3}, {%4,%5,%6,%7}, {%8,%9}, {%0,%1,%2,%3};" \
        : "+f"((ac)[0]), "+f"((ac)[1]), "+f"((ac)[2]), "+f"((ac)[3]) \
        : "r"(a0), "r"(a1), "r"(a2), "r"(a3), "r"(b0), "r"(b1))

__global__ void __launch_bounds__(256)
k_linear_pair(const uint2* __restrict__ Aa0, const uint2* __restrict__ Ab0,
              const uint2* __restrict__ W0, const float* __restrict__ b0,
              float* __restrict__ o0, uint2* __restrict__ o20,
              const uint2* __restrict__ Aa1, const uint2* __restrict__ Ab1,
              const uint2* __restrict__ W1, const float* __restrict__ b1,
              float* __restrict__ o1, uint2* __restrict__ o21,
              int softmax_y) {
    __shared__ uint2 As2[64 * KSTR];     // 10 KB
    __shared__ uint2 Bs2[128 * KSTR];    // 20 KB

    int y = blockIdx.y;
    const uint2* A2a = (y == 0) ? Aa0 : Aa1;
    const uint2* A2b = (y == 0) ? Ab0 : Ab1;
    const uint2* W2  = (y == 0) ? W0  : W1;
    const float* bias = (y == 0) ? b0 : b1;
    float* out  = (y == 0) ? o0  : o1;
    uint2* out2 = (y == 0) ? o20 : o21;
    int dosm = (y == softmax_y);

    int tx = threadIdx.x;
    int lane = tx & 31;
    int warp = tx >> 5;
    int warpM = warp >> 2;
    int warpN = warp & 3;
    int lq = lane >> 2;
    int lr = lane & 3;
    int r0 = blockIdx.x * 64;

    float acc[2][4][4];
#pragma unroll
    for (int mi = 0; mi < 2; mi++)
#pragma unroll
        for (int nj = 0; nj < 4; nj++)
#pragma unroll
            for (int q = 0; q < 4; q++) acc[mi][nj][q] = 0.f;

    for (int kc = 0; kc < 8; kc++) {            // 8 chunks of K=32 (16 pairs)
        const uint2* Asrc = (kc < 4) ? A2a : A2b;
        int wbase = (kc < 4) ? 0 : Dt * DP2;
        int kb = (kc & 3) * 16;                 // pair offset within row
#pragma unroll
        for (int it = 0; it < 2; it++) {
            int j = tx + it * 256;
            int row = j >> 3, kp = (j & 7) << 1;
            uint4 v = *(const uint4*)(Asrc + (size_t)(r0 + row) * DP2 + kb + kp);
            *(uint4*)&As2[row * KSTR + kp] = v;
        }
#pragma unroll
        for (int it = 0; it < 4; it++) {
            int j = tx + it * 256;
            int row = j >> 3, kp = (j & 7) << 1;
            uint4 v = *(const uint4*)(W2 + wbase + row * DP2 + kb + kp);
            *(uint4*)&Bs2[row * KSTR + kp] = v;
        }
        __syncthreads();
#pragma unroll
        for (int ks = 0; ks < 2; ks++) {        // 2 k16-steps per chunk
            int k0 = ks * 8;
            uint2 af[2][4];
#pragma unroll
            for (int mi = 0; mi < 2; mi++) {
                int row = warpM * 32 + mi * 16 + lq;
                af[mi][0] = As2[row * KSTR + k0 + lr];
                af[mi][1] = As2[(row + 8) * KSTR + k0 + lr];
                af[mi][2] = As2[row * KSTR + k0 + 4 + lr];
                af[mi][3] = As2[(row + 8) * KSTR + k0 + 4 + lr];
            }
            uint2 bf[4][2];
#pragma unroll
            for (int nj = 0; nj < 4; nj++) {
                int n = warpN * 32 + nj * 8 + lq;
                bf[nj][0] = Bs2[n * KSTR + k0 + lr];
                bf[nj][1] = Bs2[n * KSTR + k0 + 4 + lr];
            }
#pragma unroll
            for (int mi = 0; mi < 2; mi++)
#pragma unroll
                for (int nj = 0; nj < 4; nj++) {
                    MMA_BF16(acc[mi][nj],
                             af[mi][0].x, af[mi][1].x, af[mi][2].x, af[mi][3].x,
                             bf[nj][0].x, bf[nj][1].x);
                    MMA_BF16(acc[mi][nj],
                             af[mi][0].x, af[mi][1].x, af[mi][2].x, af[mi][3].x,
                             bf[nj][0].y, bf[nj][1].y);
                    MMA_BF16(acc[mi][nj],
                             af[mi][0].y, af[mi][1].y, af[mi][2].y, af[mi][3].y,
                             bf[nj][0].x, bf[nj][1].x);
                }
        }
        __syncthreads();
    }

    // ---- epilogue: bias + relu + row L2 norm (+ optional softmax/entropy) ----
    float* red = (float*)As2;             // [64][4]
    float* entbuf = red + 256;            // [8]
    float bv[4][2];
#pragma unroll
    for (int nj = 0; nj < 4; nj++) {
        int col = warpN * 32 + nj * 8 + 2 * lr;
        bv[nj][0] = bias[col];
        bv[nj][1] = bias[col + 1];
    }
    float ss[2][2];
#pragma unroll
    for (int mi = 0; mi < 2; mi++) { ss[mi][0] = 0.f; ss[mi][1] = 0.f; }
#pragma unroll
    for (int mi = 0; mi < 2; mi++)
#pragma unroll
        for (int nj = 0; nj < 4; nj++) {
            float v0 = fmaxf(acc[mi][nj][0] + bv[nj][0], 0.f);
            float v1 = fmaxf(acc[mi][nj][1] + bv[nj][1], 0.f);
            float v2 = fmaxf(acc[mi][nj][2] + bv[nj][0], 0.f);
            float v3 = fmaxf(acc[mi][nj][3] + bv[nj][1], 0.f);
            acc[mi][nj][0] = v0; acc[mi][nj][1] = v1;
            acc[mi][nj][2] = v2; acc[mi][nj][3] = v3;
            ss[mi][0] += v0 * v0 + v1 * v1;
            ss[mi][1] += v2 * v2 + v3 * v3;
        }
#pragma unroll
    for (int mi = 0; mi < 2; mi++)
#pragma unroll
        for (int h = 0; h < 2; h++) {
            float s = ss[mi][h];
            s += __shfl_xor_sync(~0u, s, 1);
            s += __shfl_xor_sync(~0u, s, 2);
            ss[mi][h] = s;
        }
    if (lr == 0) {
#pragma unroll
        for (int mi = 0; mi < 2; mi++)
#pragma unroll
            for (int h = 0; h < 2; h++) {
                int row = warpM * 32 + mi * 16 + lq + h * 8;
                red[row * 4 + warpN] = ss[mi][h];
            }
    }
    __syncthreads();
#pragma unroll
    for (int mi = 0; mi < 2; mi++) {
        int rowA = warpM * 32 + mi * 16 + lq;
        float t0 = red[rowA * 4] + red[rowA * 4 + 1] + red[rowA * 4 + 2] + red[rowA * 4 + 3];
        float t1 = red[(rowA + 8) * 4] + red[(rowA + 8) * 4 + 1] + red[(rowA + 8) * 4 + 2] + red[(rowA + 8) * 4 + 3];
        float inv0 = 1.0f / (sqrtf(t0) + 1e-9f);
        float inv1 = 1.0f / (sqrtf(t1) + 1e-9f);
#pragma unroll
        for (int nj = 0; nj < 4; nj++) {
            acc[mi][nj][0] *= inv0; acc[mi][nj][1] *= inv0;
            acc[mi][nj][2] *= inv1; acc[mi][nj][3] *= inv1;
        }
    }

    if (!dosm) {
#pragma unroll
        for (int mi = 0; mi < 2; mi++) {
            int rowA = warpM * 32 + mi * 16 + lq;
#pragma unroll
            for (int nj = 0; nj < 4; nj++) {
                int col = warpN * 32 + nj * 8 + 2 * lr;
                float2 o0v = make_float2(acc[mi][nj][0], acc[mi][nj][1]);
                float2 o1v = make_float2(acc[mi][nj][2], acc[mi][nj][3]);
                *(float2*)(out + (size_t)(r0 + rowA) * Dt + col) = o0v;
                *(float2*)(out + (size_t)(r0 + rowA + 8) * Dt + col) = o1v;
                if (out2) {
                    out2[(size_t)(r0 + rowA) * DP2 + (col >> 1)]     = split_bf16x2(o0v.x, o0v.y);
                    out2[(size_t)(r0 + rowA + 8) * DP2 + (col >> 1)] = split_bf16x2(o1v.x, o1v.y);
                }
            }
        }
        return;
    }

    // ---- softmax + entropy over each 128-wide row ----
    __syncthreads();                      // red reuse
    float mx[2][2];
#pragma unroll
    for (int mi = 0; mi < 2; mi++) {
        float m0 = -1e30f, m1 = -1e30f;
#pragma unroll
        for (int nj = 0; nj < 4; nj++) {
            m0 = fmaxf(m0, fmaxf(acc[mi][nj][0], acc[mi][nj][1]));
            m1 = fmaxf(m1, fmaxf(acc[mi][nj][2], acc[mi][nj][3]));
        }
        m0 = fmaxf(m0, __shfl_xor_sync(~0u, m0, 1));
        m0 = fmaxf(m0, __shfl_xor_sync(~0u, m0, 2));
        m1 = fmaxf(m1, __shfl_xor_sync(~0u, m1, 1));
        m1 = fmaxf(m1, __shfl_xor_sync(~0u, m1, 2));
        if (lr == 0) {
            int rowA = warpM * 32 + mi * 16 + lq;
            red[rowA * 4 + warpN] = m0;
            red[(rowA + 8) * 4 + warpN] = m1;
        }
    }
    __syncthreads();
#pragma unroll
    for (int mi = 0; mi < 2; mi++) {
        int rowA = warpM * 32 + mi * 16 + lq;
        mx[mi][0] = fmaxf(fmaxf(red[rowA * 4], red[rowA * 4 + 1]),
                          fmaxf(red[rowA * 4 + 2], red[rowA * 4 + 3]));
        mx[mi][1] = fmaxf(fmaxf(red[(rowA + 8) * 4], red[(rowA + 8) * 4 + 1]),
                          fmaxf(red[(rowA + 8) * 4 + 2], red[(rowA + 8) * 4 + 3]));
    }
    __syncthreads();
#pragma unroll
    for (int mi = 0; mi < 2; mi++) {
        float s0 = 0.f, s1 = 0.f;
#pragma unroll
        for (int nj = 0; nj < 4; nj++) {
            float e0 = expf(acc[mi][nj][0] - mx[mi][0]);
            float e1 = expf(acc[mi][nj][1] - mx[mi][0]);
            float e2 = expf(acc[mi][nj][2] - mx[mi][1]);
            float e3 = expf(acc[mi][nj][3] - mx[mi][1]);
            acc[mi][nj][0] = e0; acc[mi][nj][1] = e1;
            acc[mi][nj][2] = e2; acc[mi][nj][3] = e3;
            s0 += e0 + e1; s1 += e2 + e3;
        }
        s0 += __shfl_xor_sync(~0u, s0, 1);
        s0 += __shfl_xor_sync(~0u, s0, 2);
        s1 += __shfl_xor_sync(~0u, s1, 1);
        s1 += __shfl_xor_sync(~0u, s1, 2);
        if (lr == 0) {
            int rowA = warpM * 32 + mi * 16 + lq;
            red[rowA * 4 + warpN] = s0;
            red[(rowA + 8) * 4 + warpN] = s1;
        }
    }
    __syncthreads();
    float ent = 0.f;
#pragma unroll
    for (int mi = 0; mi < 2; mi++) {
        int rowA = warpM * 32 + mi * 16 + lq;
        float s0 = red[rowA * 4] + red[rowA * 4 + 1] + red[rowA * 4 + 2] + red[rowA * 4 + 3];
        float s1 = red[(rowA + 8) * 4] + red[(rowA + 8) * 4 + 1] + red[(rowA + 8) * 4 + 2] + red[(rowA + 8) * 4 + 3];
        float i0 = 1.0f / s0, i1 = 1.0f / s1;
#pragma unroll
        for (int nj = 0; nj < 4; nj++) {
            int col = warpN * 32 + nj * 8 + 2 * lr;
            float p0 = acc[mi][nj][0] * i0, p1 = acc[mi][nj][1] * i0;
            float p2 = acc[mi][nj][2] * i1, p3 = acc[mi][nj][3] * i1;
            ent -= p0 * logf(p0 + 1e-15f) + p1 * logf(p1 + 1e-15f)
                 + p2 * logf(p2 + 1e-15f) + p3 * logf(p3 + 1e-15f);
            *(float2*)(out + (size_t)(r0 + rowA) * Dt + col) = make_float2(p0, p1);
            *(float2*)(out + (size_t)(r0 + rowA + 8) * Dt + col) = make_float2(p2, p3);
        }
    }
#pragma unroll
    for (int off = 16; off; off >>= 1) ent += __shfl_xor_sync(~0u, ent, off);
    __syncthreads();
    if (lane == 0) entbuf[warp] = ent;
    __syncthreads();
    if (tx == 0) {
        float t = 0.f;
        for (int w = 0; w < 8; w++) t += entbuf[w];
        atomicAdd(&d_ent, (double)t);
    }
}

// warp per row r: adjS[r] = sum_{m in csr[r]} S[m]  AND  E += dot(S[r], adjS[r])
__global__ void k_adjS_E(const float* __restrict__ S, float* __restrict__ adjS) {
    __shared__ float esm[8];
    int warp_l = threadIdx.x >> 5;
    int warp = (blockIdx.x * blockDim.x + threadIdx.x) >> 5;
    int lane = threadIdx.x & 31;
    float loc = 0.f;
    if (warp < BN) {
        int c = d_csr_cnt[warp];
        int cl = c < CAP ? c : CAP;
        const int* ip = d_csr_idx + warp * CAP;
        float4 acc = make_float4(0.f, 0.f, 0.f, 0.f);
        int e = 0;
        for (; e + 2 <= cl; e += 2) {
            int s0 = ip[e], s1 = ip[e + 1];
            float4 v0 = *(const float4*)(S + (size_t)s0 * Dt + (lane << 2));
            float4 v1 = *(const float4*)(S + (size_t)s1 * Dt + (lane << 2));
            acc.x += v0.x + v1.x; acc.y += v0.y + v1.y;
            acc.z += v0.z + v1.z; acc.w += v0.w + v1.w;
        }
        if (e < cl) {
            int s = ip[e];
            float4 v = *(const float4*)(S + (size_t)s * Dt + (lane << 2));
            acc.x += v.x; acc.y += v.y; acc.z += v.z; acc.w += v.w;
        }
        *(float4*)(adjS + (size_t)warp * Dt + (lane << 2)) = acc;
        float4 sr = *(const float4*)(S + (size_t)warp * Dt + (lane << 2));
        loc = sr.x * acc.x + sr.y * acc.y + sr.z * acc.z + sr.w * acc.w;
#pragma unroll
        for (int off = 16; off; off >>= 1) loc += __shfl_xor_sync(~0u, loc, off);
    }
    if (lane == 0) esm[warp_l] = loc;
    __syncthreads();
    if (threadIdx.x == 0) {
        float t = 0.f;
        for (int w = 0; w < 8; w++) t += esm[w];
        atomicAdd(&d_E, (double)t);
    }
}

// three batched A^T@B products in one launch: z selects (A,B,C) operands.
#define AR 32
#define AI 4
__global__ void k_atb3(const float* __restrict__ S, const float* __restrict__ hemb,
                       const float* __restrict__ adjS, float* __restrict__ hP,
                       float* __restrict__ aP, float* __restrict__ StS) {
    __shared__ float As[AR][Dt];
    __shared__ float Bs[AR][Dt];
    int b = blockIdx.y;
    int z = blockIdx.z;
    const float* A  = S;
    const float* Bm = (z == 0) ? hemb : (z == 1) ? adjS : S;
    float* C        = (z == 0) ? hP   : (z == 1) ? aP   : StS;
    ull acc[8][4];
#pragma unroll
    for (int i = 0; i < 8; i++)
#pragma unroll
        for (int j = 0; j < 4; j++) acc[i][j] = 0ull;
    int tk = threadIdx.x >> 4, td = threadIdx.x & 15;
    for (int c = 0; c < AI; c++) {
        int n0 = (blockIdx.x * AI + c) * AR;
        const float* Ap = A  + ((size_t)b * Nt + n0) * Dt;
        const float* Bp = Bm + ((size_t)b * Nt + n0) * Dt;
        __syncthreads();
        for (int t = threadIdx.x; t < AR * 32; t += 256) {
            int r = t >> 5, k4 = (t & 31) << 2;
            *(float4*)&As[r][k4] = *(const float4*)(Ap + r * Dt + k4);
            *(float4*)&Bs[r][k4] = *(const float4*)(Bp + r * Dt + k4);
        }
        __syncthreads();
        for (int n = 0; n < AR; n++) {
            float a[8];
            *(float4*)&a[0] = *(const float4*)&As[n][tk * 8];
            *(float4*)&a[4] = *(const float4*)&As[n][tk * 8 + 4];
            const ulonglong2* bp = (const ulonglong2*)&Bs[n][td * 8];
            ulonglong2 b01 = bp[0];
            ulonglong2 b23 = bp[1];
            ull ad[8];
#pragma unroll
            for (int i = 0; i < 8; i++) {
                unsigned int ab = __float_as_uint(a[i]);
                asm("mov.b64 %0, {%1, %1};" : "=l"(ad[i]) : "r"(ab));
            }
#pragma unroll
            for (int i = 0; i < 8; i++) {
                asm("fma.rn.f32x2 %0, %1, %2, %0;" : "+l"(acc[i][0]) : "l"(ad[i]), "l"(b01.x));
                asm("fma.rn.f32x2 %0, %1, %2, %0;" : "+l"(acc[i][1]) : "l"(ad[i]), "l"(b01.y));
                asm("fma.rn.f32x2 %0, %1, %2, %0;" : "+l"(acc[i][2]) : "l"(ad[i]), "l"(b23.x));
                asm("fma.rn.f32x2 %0, %1, %2, %0;" : "+l"(acc[i][3]) : "l"(ad[i]), "l"(b23.y));
            }
        }
    }
    size_t cb = (size_t)b * Dt * Dt;
#pragma unroll
    for (int i = 0; i < 8; i++)
#pragma unroll
        for (int j = 0; j < 4; j++) {
            float lo, hi;
            asm("mov.b64 {%0, %1}, %2;" : "=f"(lo), "=f"(hi) : "l"(acc[i][j]));
            atomicAdd(&C[cb + (size_t)(tk * 8 + i) * Dt + (td * 8 + 2 * j)], lo);
            atomicAdd(&C[cb + (size_t)(tk * 8 + i) * Dt + (td * 8 + 2 * j + 1)], hi);
        }
}

__global__ void k_sumcnt() {
    __shared__ float sm[8];
    int i = blockIdx.x * blockDim.x + threadIdx.x;
    float v = (i < BN) ? (float)d_csr_cnt[i] : 0.f;
#pragma unroll
    for (int off = 16; off; off >>= 1) v += __shfl_xor_sync(~0u, v, off);
    int wid = threadIdx.x >> 5, lane = threadIdx.x & 31;
    if (lane == 0) sm[wid] = v;
    __syncthreads();
    if (threadIdx.x == 0) {
        float t = 0.f;
        for (int w = 0; w < 8; w++) t += sm[w];
        atomicAdd(&d_nnz, (double)t);
    }
}

__global__ void k_sumsq() {
    __shared__ float sm[8];
    int i = blockIdx.x * blockDim.x + threadIdx.x;
    float x = (i < Bt * Dt * Dt) ? d_StS[i] : 0.f;
    float v = x * x;
#pragma unroll
    for (int off = 16; off; off >>= 1) v += __shfl_xor_sync(~0u, v, off);
    int wid = threadIdx.x >> 5, lane = threadIdx.x & 31;
    if (lane == 0) sm[wid] = v;
    __syncthreads();
    if (threadIdx.x == 0) {
        float t = 0.f;
        for (int w = 0; w < 8; w++) t += sm[w];
        atomicAdd(&d_F, (double)t);
    }
}

__global__ void k_final(float* out) {
    double l2 = d_nnz - 2.0 * d_E + d_F;
    if (l2 < 0.0) l2 = 0.0;
    out[2 * Bt * Dt * Dt]     = (float)(sqrt(l2) / ((double)Bt * Nt * Nt));
    out[2 * Bt * Dt * Dt + 1] = (float)(d_ent / (double)BN);
}

// ---------------- launch ----------------

extern "C" void kernel_launch(void* const* d_in, const int* in_sizes, int n_in,
                              void* d_out, int out_size) {
    const float* x    = (const float*)d_in[0];
    const float* adj  = (const float*)d_in[1];
    const float* We1l = (const float*)d_in[2];
    const float* be1  = (const float*)d_in[3];
    const float* We1r = (const float*)d_in[4];
    const float* We2l = (const float*)d_in[5];
    const float* be2  = (const float*)d_in[6];
    const float* We2r = (const float*)d_in[7];
    const float* Wa1l = (const float*)d_in[8];
    const float* ba1  = (const float*)d_in[9];
    const float* Wa1r = (const float*)d_in[10];
    const float* Wa2l = (const float*)d_in[11];
    const float* ba2  = (const float*)d_in[12];
    const float* Wa2r = (const float*)d_in[13];
    float* out = (float*)d_out;

    void* p;
    cudaGetSymbolAddress(&p, d_h1);    float* h1    = (float*)p;
    cudaGetSymbolAddress(&p, d_a1);    float* a1    = (float*)p;
    cudaGetSymbolAddress(&p, d_hemb);  float* hemb  = (float*)p;
    cudaGetSymbolAddress(&p, d_S);     float* S     = (float*)p;
    cudaGetSymbolAddress(&p, d_adjS);  float* adjS  = (float*)p;
    cudaGetSymbolAddress(&p, d_StS);   float* StS   = (float*)p;
    cudaGetSymbolAddress(&p, d_x2);    uint2* x2    = (uint2*)p;
    cudaGetSymbolAddress(&p, d_agg2);  uint2* agg2  = (uint2*)p;
    cudaGetSymbolAddress(&p, d_agg2a); uint2* agg2a = (uint2*)p;
    cudaGetSymbolAddress(&p, d_h1s);   uint2* h1s   = (uint2*)p;
    cudaGetSymbolAddress(&p, d_a1s);   uint2* a1s   = (uint2*)p;
    cudaGetSymbolAddress(&p, d_Ws);    uint2* Ws    = (uint2*)p;
    const int WSZ = 2 * Dt * DP2;

    k_clear<<<256, 256>>>(out, out_size);

    // CSR/CSC build + all bf16 splits, grid-packed into ONE launch
    k_build_split<<<BN + 2048 + 128, 256>>>(adj, x, x2,
                                            We1l, We1r, Wa1l, Wa1r,
                                            We2l, We2r, Wa2l, Wa2r);

    // agg1 = adj^T x / deg  (shared by emb1 and assign1), split form
    k_spmm<<<BN / 8, 256>>>(x, nullptr, agg2, 0, 1);

    // layer-1: both linears grid-packed into one launch
    k_linear_pair<<<dim3(BN / 64, 2), 256>>>(
        agg2, x2, Ws + 0 * WSZ, be1, h1, h1s,
        agg2, x2, Ws + 1 * WSZ, ba1, a1, a1s, -1);

    // layer-2 gathers fused (shared CSC index reads)
    k_spmm_dual<<<BN / 8, 256>>>(h1, a1, agg2, agg2a);

    // layer-2: both linears grid-packed; y=1 (assign) fuses softmax+entropy
    k_linear_pair<<<dim3(BN / 64, 2), 256>>>(
        agg2,  h1s, Ws + 2 * WSZ, be2, hemb, nullptr,
        agg2a, a1s, Ws + 3 * WSZ, ba2, S, nullptr, 1);

    // adjS = adj @ S (CSR gather) fused with E = sum_n dot(S[n], adjS[n])
    k_adjS_E<<<BN / 8, 256>>>(S, adjS);

    // three pooled products in ONE launch (384 blocks, fills the chip)
    k_atb3<<<dim3(Nt / (AR * AI), Bt, 3), 256>>>(S, hemb, adjS, out, out + Bt * Dt * Dt, StS);

    k_sumcnt<<<BN / 256, 256>>>();
    k_sumsq<<<(Bt * Dt * Dt) / 256, 256>>>();
    k_final<<<1, 1>>>(out);
}

// round 15
// speedup vs baseline: 1.0378x; 1.0038x over previous
#include <cuda_runtime.h>
#include <math.h>

#define Bt 8
#define Nt 2048
#define Dt 128
#define DP2 64             // bf16 pairs per row (Dt/2)
#define BN 16384           // Bt*Nt
#define CAP 96             // max in/out degree capacity (mean ~20.5, sigma ~4.5)

typedef unsigned long long ull;
typedef unsigned int uint;

// ---------------- scratch (static device allocations, allowed) ----------------
__device__ int   d_csc_cnt[BN];
__device__ int   d_csr_cnt[BN];
__device__ int   d_csc_idx[BN * CAP];
__device__ int   d_csr_idx[BN * CAP];
__device__ float d_h1   [BN * Dt];
__device__ float d_a1   [BN * Dt];
__device__ float d_hemb [BN * Dt];
__device__ float d_S    [BN * Dt];
__device__ float d_adjS [BN * Dt];
__device__ float d_StS  [Bt * Dt * Dt];
// bf16x2 split planes: uint2 per element-pair {hi(2xbf16), lo(2xbf16)}
__device__ uint2 d_x2   [BN * DP2];
__device__ uint2 d_agg2 [BN * DP2];
__device__ uint2 d_agg2a[BN * DP2];
__device__ uint2 d_h1s  [BN * DP2];
__device__ uint2 d_a1s  [BN * DP2];
__device__ uint2 d_Ws[4][2 * Dt * DP2];  // per layer: Wl rows 0..127, Wr rows 128..255
__device__ double d_E, d_F, d_nnz, d_ent;

// split two consecutive floats into {hi bf16x2, lo bf16x2}; element0 in low half
__device__ __forceinline__ uint2 split_bf16x2(float v0, float v1) {
    uint hi, lo;
    asm("cvt.rn.bf16x2.f32 %0, %1, %2;" : "=r"(hi) : "f"(v1), "f"(v0));
    float h0 = __uint_as_float(hi << 16);
    float h1 = __uint_as_float(hi & 0xFFFF0000u);
    float r0 = v0 - h0, r1 = v1 - h1;
    asm("cvt.rn.bf16x2.f32 %0, %1, %2;" : "=r"(lo) : "f"(r1), "f"(r0));
    return make_uint2(hi, lo);
}

// ---------------- kernels ----------------

__global__ void k_clear(float* out, int osz) {
    int stride = gridDim.x * blockDim.x;
    int i0 = blockIdx.x * blockDim.x + threadIdx.x;
    for (int i = i0; i < BN; i += stride) { d_csc_cnt[i] = 0; d_csr_cnt[i] = 0; }
    for (int i = i0; i < Bt * Dt * Dt; i += stride) d_StS[i] = 0.f;
    for (int i = i0; i < osz; i += stride) out[i] = 0.f;
    if (i0 == 0) { d_E = 0.0; d_F = 0.0; d_nnz = 0.0; d_ent = 0.0; }
}

// ONE launch, grid-packed independent work:
//   blocks [0, BN)            : build CSC/CSR from adjacency row
//   blocks [BN, BN+2048)      : split x into bf16x2 planes
//   blocks [BN+2048, BN+2176) : split the 4 weight pairs
__global__ void k_build_split(const float* __restrict__ adj,
                              const float* __restrict__ x, uint2* __restrict__ x2,
                              const float* __restrict__ W0l, const float* __restrict__ W0r,
                              const float* __restrict__ W1l, const float* __restrict__ W1r,
                              const float* __restrict__ W2l, const float* __restrict__ W2r,
                              const float* __restrict__ W3l, const float* __restrict__ W3r) {
    if (blockIdx.x < BN) {
        int row = blockIdx.x;                 // flat b*Nt + i
        int base = row & ~(Nt - 1);           // b*Nt
        const float4* ar = (const float4*)(adj + (size_t)row * Nt);
        for (int j4 = threadIdx.x; j4 < Nt / 4; j4 += blockDim.x) {
            float4 v = ar[j4];
            int j = j4 << 2;
#pragma unroll
            for (int u = 0; u < 4; u++) {
                float f = (u == 0) ? v.x : (u == 1) ? v.y : (u == 2) ? v.z : v.w;
                if (f != 0.0f) {
                    int t = base + j + u;
                    int p = atomicAdd(&d_csc_cnt[t], 1);
                    if (p < CAP) d_csc_idx[t * CAP + p] = row;
                    int q = atomicAdd(&d_csr_cnt[row], 1);
                    if (q < CAP) d_csr_idx[row * CAP + q] = t;
                }
            }
        }
    } else if (blockIdx.x < BN + 2048) {
        int i = (blockIdx.x - BN) * blockDim.x + threadIdx.x;   // float4 index
        float4 v = *(const float4*)(x + i * 4);
        uint2 s[2] = {split_bf16x2(v.x, v.y), split_bf16x2(v.z, v.w)};
        *(uint4*)(x2 + i * 2) = *(uint4*)&s[0];
    } else {
        int wb = blockIdx.x - BN - 2048;
        int layer = wb >> 5;
        int i = (wb & 31) * blockDim.x + threadIdx.x;           // 0 .. 2*Dt*Dt/4-1
        const float* Wl = (layer == 0) ? W0l : (layer == 1) ? W1l : (layer == 2) ? W2l : W3l;
        const float* Wr = (layer == 0) ? W0r : (layer == 1) ? W1r : (layer == 2) ? W2r : W3r;
        const float* src = (i < Dt * Dt / 4) ? Wl : Wr;
        int off = (i < Dt * Dt / 4) ? i * 4 : (i * 4 - Dt * Dt);
        float4 v = *(const float4*)(src + off);
        uint2 s[2] = {split_bf16x2(v.x, v.y), split_bf16x2(v.z, v.w)};
        *(uint4*)(d_Ws[layer] + i * 2) = *(uint4*)&s[0];
    }
}

// warp per output row: CSC mean-gather of X, writes bf16x2 split form
__global__ void k_spmm(const float* __restrict__ X, float* __restrict__ outf,
                       uint2* __restrict__ out2, int use_csr, int scale) {
    int warp = (blockIdx.x * blockDim.x + threadIdx.x) >> 5;
    int lane = threadIdx.x & 31;
    if (warp >= BN) return;
    const int* cntp = use_csr ? d_csr_cnt : d_csc_cnt;
    const int* idxp = use_csr ? d_csr_idx : d_csc_idx;
    int c = cntp[warp];
    int cl = c < CAP ? c : CAP;
    const int* ip = idxp + warp * CAP;
    float4 acc = make_float4(0.f, 0.f, 0.f, 0.f);
    int e = 0;
    for (; e + 4 <= cl; e += 4) {
        int s0 = ip[e], s1 = ip[e + 1], s2 = ip[e + 2], s3 = ip[e + 3];
        float4 v0 = *(const float4*)(X + (size_t)s0 * Dt + (lane << 2));
        float4 v1 = *(const float4*)(X + (size_t)s1 * Dt + (lane << 2));
        float4 v2 = *(const float4*)(X + (size_t)s2 * Dt + (lane << 2));
        float4 v3 = *(const float4*)(X + (size_t)s3 * Dt + (lane << 2));
        acc.x += (v0.x + v1.x) + (v2.x + v3.x);
        acc.y += (v0.y + v1.y) + (v2.y + v3.y);
        acc.z += (v0.z + v1.z) + (v2.z + v3.z);
        acc.w += (v0.w + v1.w) + (v2.w + v3.w);
    }
    for (; e < cl; e++) {
        int s = ip[e];
        float4 v = *(const float4*)(X + (size_t)s * Dt + (lane << 2));
        acc.x += v.x; acc.y += v.y; acc.z += v.z; acc.w += v.w;
    }
    if (scale) {
        float sc = 1.0f / (float)(c > 1 ? c : 1);
        acc.x *= sc; acc.y *= sc; acc.z *= sc; acc.w *= sc;
    }
    if (outf)
        *(float4*)(outf + (size_t)warp * Dt + (lane << 2)) = acc;
    if (out2) {
        uint2 s[2] = {split_bf16x2(acc.x, acc.y), split_bf16x2(acc.z, acc.w)};
        *(uint4*)(out2 + (size_t)warp * DP2 + (lane << 1)) = *(uint4*)&s[0];
    }
}

// warp per row: dual CSC mean-gather of H and A in one pass (shared index list)
__global__ void k_spmm_dual(const float* __restrict__ H, const float* __restrict__ A,
                            uint2* __restrict__ outH, uint2* __restrict__ outA) {
    int warp = (blockIdx.x * blockDim.x + threadIdx.x) >> 5;
    int lane = threadIdx.x & 31;
    if (warp >= BN) return;
    int c = d_csc_cnt[warp];
    int cl = c < CAP ? c : CAP;
    const int* ip = d_csc_idx + warp * CAP;
    float4 ah = make_float4(0.f, 0.f, 0.f, 0.f);
    float4 aa = make_float4(0.f, 0.f, 0.f, 0.f);
    int e = 0;
    for (; e + 2 <= cl; e += 2) {
        int s0 = ip[e], s1 = ip[e + 1];
        float4 h0 = *(const float4*)(H + (size_t)s0 * Dt + (lane << 2));
        float4 a0 = *(const float4*)(A + (size_t)s0 * Dt + (lane << 2));
        float4 h1 = *(const float4*)(H + (size_t)s1 * Dt + (lane << 2));
        float4 a1 = *(const float4*)(A + (size_t)s1 * Dt + (lane << 2));
        ah.x += h0.x + h1.x; ah.y += h0.y + h1.y; ah.z += h0.z + h1.z; ah.w += h0.w + h1.w;
        aa.x += a0.x + a1.x; aa.y += a0.y + a1.y; aa.z += a0.z + a1.z; aa.w += a0.w + a1.w;
    }
    if (e < cl) {
        int s = ip[e];
        float4 h0 = *(const float4*)(H + (size_t)s * Dt + (lane << 2));
        float4 a0 = *(const float4*)(A + (size_t)s * Dt + (lane << 2));
        ah.x += h0.x; ah.y += h0.y; ah.z += h0.z; ah.w += h0.w;
        aa.x += a0.x; aa.y += a0.y; aa.z += a0.z; aa.w += a0.w;
    }
    float sc = 1.0f / (float)(c > 1 ? c : 1);
    ah.x *= sc; ah.y *= sc; ah.z *= sc; ah.w *= sc;
    aa.x *= sc; aa.y *= sc; aa.z *= sc; aa.w *= sc;
    uint2 sh[2] = {split_bf16x2(ah.x, ah.y), split_bf16x2(ah.z, ah.w)};
    uint2 sa[2] = {split_bf16x2(aa.x, aa.y), split_bf16x2(aa.z, aa.w)};
    *(uint4*)(outH + (size_t)warp * DP2 + (lane << 1)) = *(uint4*)&sh[0];
    *(uint4*)(outA + (size_t)warp * DP2 + (lane << 1)) = *(uint4*)&sa[0];
}

// ---------------------------------------------------------------------------
// fused dual-GEMM via bf16x2 tensor cores (3-MMA split) on PRE-SPLIT inputs,
// grid-packed: blockIdx.y in {0,1} selects one of two independent problems.
//   out = l2norm(relu(agg @ Wl^T + b + xin @ Wr^T))    [+ optional softmax+ent]
// Block: 64 rows x 128 cols, 256 threads = 8 warps (2M x 4N), warp 32x32.
// mma.m16n8k16 bf16, acc += Ah*Bh + Ah*Bl + Al*Bh.
// A frag (k-pair units): a0=(g,p) a1=(g+8,p) a2=(g,p+4) a3=(g+8,p+4)
// __launch_bounds__(256,3): cap regs ~85 so 3 blocks/SM fit the RF (was 94 -> 2).
// ---------------------------------------------------------------------------
#define KSTR 20
#define MMA_BF16(ac, a0, a1, a2, a3, b0, b1) \
    asm volatile("mma.sync.aligned.m16n8k16.row.col.f32.bf16.bf16.f32 " \
        "{%0,%1,%2,%3}, {%4,%5,%6,%7}, {%8,%9}, {%0,%1,%2,%3};" \
        : "+f"((ac)[0]), "+f"((ac)[1]), "+f"((ac)[2]), "+f"((ac)[3]) \
        : "r"(a0), "r"(a1), "r"(a2), "r"(a3), "r"(b0), "r"(b1))

__global__ void __launch_bounds__(256, 3)
k_linear_pair(const uint2* __restrict__ Aa0, const uint2* __restrict__ Ab0,
              const uint2* __restrict__ W0, const float* __restrict__ b0,
              float* __restrict__ o0, uint2* __restrict__ o20,
              const uint2* __restrict__ Aa1, const uint2* __restrict__ Ab1,
              const uint2* __restrict__ W1, const float* __restrict__ b1,
              float* __restrict__ o1, uint2* __restrict__ o21,
              int softmax_y) {
    __shared__ uint2 As2[64 * KSTR];     // 10 KB
    __shared__ uint2 Bs2[128 * KSTR];    // 20 KB

    int y = blockIdx.y;
    const uint2* A2a = (y == 0) ? Aa0 : Aa1;
    const uint2* A2b = (y == 0) ? Ab0 : Ab1;
    const uint2* W2  = (y == 0) ? W0  : W1;
    const float* bias = (y == 0) ? b0 : b1;
    float* out  = (y == 0) ? o0  : o1;
    uint2* out2 = (y == 0) ? o20 : o21;
    int dosm = (y == softmax_y);

    int tx = threadIdx.x;
    int lane = tx & 31;
    int warp = tx >> 5;
    int warpM = warp >> 2;
    int warpN = warp & 3;
    int lq = lane >> 2;
    int lr = lane & 3;
    int r0 = blockIdx.x * 64;

    float acc[2][4][4];
#pragma unroll
    for (int mi = 0; mi < 2; mi++)
#pragma unroll
        for (int nj = 0; nj < 4; nj++)
#pragma unroll
            for (int q = 0; q < 4; q++) acc[mi][nj][q] = 0.f;

    for (int kc = 0; kc < 8; kc++) {            // 8 chunks of K=32 (16 pairs)
        const uint2* Asrc = (kc < 4) ? A2a : A2b;
        int wbase = (kc < 4) ? 0 : Dt * DP2;
        int kb = (kc & 3) * 16;                 // pair offset within row
#pragma unroll
        for (int it = 0; it < 2; it++) {
            int j = tx + it * 256;
            int row = j >> 3, kp = (j & 7) << 1;
            uint4 v = *(const uint4*)(Asrc + (size_t)(r0 + row) * DP2 + kb + kp);
            *(uint4*)&As2[row * KSTR + kp] = v;
        }
#pragma unroll
        for (int it = 0; it < 4; it++) {
            int j = tx + it * 256;
            int row = j >> 3, kp = (j & 7) << 1;
            uint4 v = *(const uint4*)(W2 + wbase + row * DP2 + kb + kp);
            *(uint4*)&Bs2[row * KSTR + kp] = v;
        }
        __syncthreads();
#pragma unroll
        for (int ks = 0; ks < 2; ks++) {        // 2 k16-steps per chunk
            int k0 = ks * 8;
            uint2 af[2][4];
#pragma unroll
            for (int mi = 0; mi < 2; mi++) {
                int row = warpM * 32 + mi * 16 + lq;
                af[mi][0] = As2[row * KSTR + k0 + lr];
                af[mi][1] = As2[(row + 8) * KSTR + k0 + lr];
                af[mi][2] = As2[row * KSTR + k0 + 4 + lr];
                af[mi][3] = As2[(row + 8) * KSTR + k0 + 4 + lr];
            }
            uint2 bf[4][2];
#pragma unroll
            for (int nj = 0; nj < 4; nj++) {
                int n = warpN * 32 + nj * 8 + lq;
                bf[nj][0] = Bs2[n * KSTR + k0 + lr];
                bf[nj][1] = Bs2[n * KSTR + k0 + 4 + lr];
            }
#pragma unroll
            for (int mi = 0; mi < 2; mi++)
#pragma unroll
                for (int nj = 0; nj < 4; nj++) {
                    MMA_BF16(acc[mi][nj],
                             af[mi][0].x, af[mi][1].x, af[mi][2].x, af[mi][3].x,
                             bf[nj][0].x, bf[nj][1].x);
                    MMA_BF16(acc[mi][nj],
                             af[mi][0].x, af[mi][1].x, af[mi][2].x, af[mi][3].x,
                             bf[nj][0].y, bf[nj][1].y);
                    MMA_BF16(acc[mi][nj],
                             af[mi][0].y, af[mi][1].y, af[mi][2].y, af[mi][3].y,
                             bf[nj][0].x, bf[nj][1].x);
                }
        }
        __syncthreads();
    }

    // ---- epilogue: bias + relu + row L2 norm (+ optional softmax/entropy) ----
    float* red = (float*)As2;             // [64][4]
    float* entbuf = red + 256;            // [8]
    float bv[4][2];
#pragma unroll
    for (int nj = 0; nj < 4; nj++) {
        int col = warpN * 32 + nj * 8 + 2 * lr;
        bv[nj][0] = bias[col];
        bv[nj][1] = bias[col + 1];
    }
    float ss[2][2];
#pragma unroll
    for (int mi = 0; mi < 2; mi++) { ss[mi][0] = 0.f; ss[mi][1] = 0.f; }
#pragma unroll
    for (int mi = 0; mi < 2; mi++)
#pragma unroll
        for (int nj = 0; nj < 4; nj++) {
            float v0 = fmaxf(acc[mi][nj][0] + bv[nj][0], 0.f);
            float v1 = fmaxf(acc[mi][nj][1] + bv[nj][1], 0.f);
            float v2 = fmaxf(acc[mi][nj][2] + bv[nj][0], 0.f);
            float v3 = fmaxf(acc[mi][nj][3] + bv[nj][1], 0.f);
            acc[mi][nj][0] = v0; acc[mi][nj][1] = v1;
            acc[mi][nj][2] = v2; acc[mi][nj][3] = v3;
            ss[mi][0] += v0 * v0 + v1 * v1;
            ss[mi][1] += v2 * v2 + v3 * v3;
        }
#pragma unroll
    for (int mi = 0; mi < 2; mi++)
#pragma unroll
        for (int h = 0; h < 2; h++) {
            float s = ss[mi][h];
            s += __shfl_xor_sync(~0u, s, 1);
            s += __shfl_xor_sync(~0u, s, 2);
            ss[mi][h] = s;
        }
    if (lr == 0) {
#pragma unroll
        for (int mi = 0; mi < 2; mi++)
#pragma unroll
            for (int h = 0; h < 2; h++) {
                int row = warpM * 32 + mi * 16 + lq + h * 8;
                red[row * 4 + warpN] = ss[mi][h];
            }
    }
    __syncthreads();
#pragma unroll
    for (int mi = 0; mi < 2; mi++) {
        int rowA = warpM * 32 + mi * 16 + lq;
        float t0 = red[rowA * 4] + red[rowA * 4 + 1] + red[rowA * 4 + 2] + red[rowA * 4 + 3];
        float t1 = red[(rowA + 8) * 4] + red[(rowA + 8) * 4 + 1] + red[(rowA + 8) * 4 + 2] + red[(rowA + 8) * 4 + 3];
        float inv0 = 1.0f / (sqrtf(t0) + 1e-9f);
        float inv1 = 1.0f / (sqrtf(t1) + 1e-9f);
#pragma unroll
        for (int nj = 0; nj < 4; nj++) {
            acc[mi][nj][0] *= inv0; acc[mi][nj][1] *= inv0;
            acc[mi][nj][2] *= inv1; acc[mi][nj][3] *= inv1;
        }
    }

    if (!dosm) {
#pragma unroll
        for (int mi = 0; mi < 2; mi++) {
            int rowA = warpM * 32 + mi * 16 + lq;
#pragma unroll
            for (int nj = 0; nj < 4; nj++) {
                int col = warpN * 32 + nj * 8 + 2 * lr;
                float2 o0v = make_float2(acc[mi][nj][0], acc[mi][nj][1]);
                float2 o1v = make_float2(acc[mi][nj][2], acc[mi][nj][3]);
                *(float2*)(out + (size_t)(r0 + rowA) * Dt + col) = o0v;
                *(float2*)(out + (size_t)(r0 + rowA + 8) * Dt + col) = o1v;
                if (out2) {
                    out2[(size_t)(r0 + rowA) * DP2 + (col >> 1)]     = split_bf16x2(o0v.x, o0v.y);
                    out2[(size_t)(r0 + rowA + 8) * DP2 + (col >> 1)] = split_bf16x2(o1v.x, o1v.y);
                }
            }
        }
        return;
    }

    // ---- softmax + entropy over each 128-wide row ----
    __syncthreads();                      // red reuse
    float mx[2][2];
#pragma unroll
    for (int mi = 0; mi < 2; mi++) {
        float m0 = -1e30f, m1 = -1e30f;
#pragma unroll
        for (int nj = 0; nj < 4; nj++) {
            m0 = fmaxf(m0, fmaxf(acc[mi][nj][0], acc[mi][nj][1]));
            m1 = fmaxf(m1, fmaxf(acc[mi][nj][2], acc[mi][nj][3]));
        }
        m0 = fmaxf(m0, __shfl_xor_sync(~0u, m0, 1));
        m0 = fmaxf(m0, __shfl_xor_sync(~0u, m0, 2));
        m1 = fmaxf(m1, __shfl_xor_sync(~0u, m1, 1));
        m1 = fmaxf(m1, __shfl_xor_sync(~0u, m1, 2));
        if (lr == 0) {
            int rowA = warpM * 32 + mi * 16 + lq;
            red[rowA * 4 + warpN] = m0;
            red[(rowA + 8) * 4 + warpN] = m1;
        }
    }
    __syncthreads();
#pragma unroll
    for (int mi = 0; mi < 2; mi++) {
        int rowA = warpM * 32 + mi * 16 + lq;
        mx[mi][0] = fmaxf(fmaxf(red[rowA * 4], red[rowA * 4 + 1]),
                          fmaxf(red[rowA * 4 + 2], red[rowA * 4 + 3]));
        mx[mi][1] = fmaxf(fmaxf(red[(rowA + 8) * 4], red[(rowA + 8) * 4 + 1]),
                          fmaxf(red[(rowA + 8) * 4 + 2], red[(rowA + 8) * 4 + 3]));
    }
    __syncthreads();
#pragma unroll
    for (int mi = 0; mi < 2; mi++) {
        float s0 = 0.f, s1 = 0.f;
#pragma unroll
        for (int nj = 0; nj < 4; nj++) {
            float e0 = expf(acc[mi][nj][0] - mx[mi][0]);
            float e1 = expf(acc[mi][nj][1] - mx[mi][0]);
            float e2 = expf(acc[mi][nj][2] - mx[mi][1]);
            float e3 = expf(acc[mi][nj][3] - mx[mi][1]);
            acc[mi][nj][0] = e0; acc[mi][nj][1] = e1;
            acc[mi][nj][2] = e2; acc[mi][nj][3] = e3;
            s0 += e0 + e1; s1 += e2 + e3;
        }
        s0 += __shfl_xor_sync(~0u, s0, 1);
        s0 += __shfl_xor_sync(~0u, s0, 2);
        s1 += __shfl_xor_sync(~0u, s1, 1);
        s1 += __shfl_xor_sync(~0u, s1, 2);
        if (lr == 0) {
            int rowA = warpM * 32 + mi * 16 + lq;
            red[rowA * 4 + warpN] = s0;
            red[(rowA + 8) * 4 + warpN] = s1;
        }
    }
    __syncthreads();
    float ent = 0.f;
#pragma unroll
    for (int mi = 0; mi < 2; mi++) {
        int rowA = warpM * 32 + mi * 16 + lq;
        float s0 = red[rowA * 4] + red[rowA * 4 + 1] + red[rowA * 4 + 2] + red[rowA * 4 + 3];
        float s1 = red[(rowA + 8) * 4] + red[(rowA + 8) * 4 + 1] + red[(rowA + 8) * 4 + 2] + red[(rowA + 8) * 4 + 3];
        float i0 = 1.0f / s0, i1 = 1.0f / s1;
#pragma unroll
        for (int nj = 0; nj < 4; nj++) {
            int col = warpN * 32 + nj * 8 + 2 * lr;
            float p0 = acc[mi][nj][0] * i0, p1 = acc[mi][nj][1] * i0;
            float p2 = acc[mi][nj][2] * i1, p3 = acc[mi][nj][3] * i1;
            ent -= p0 * logf(p0 + 1e-15f) + p1 * logf(p1 + 1e-15f)
                 + p2 * logf(p2 + 1e-15f) + p3 * logf(p3 + 1e-15f);
            *(float2*)(out + (size_t)(r0 + rowA) * Dt + col) = make_float2(p0, p1);
            *(float2*)(out + (size_t)(r0 + rowA + 8) * Dt + col) = make_float2(p2, p3);
        }
    }
#pragma unroll
    for (int off = 16; off; off >>= 1) ent += __shfl_xor_sync(~0u, ent, off);
    __syncthreads();
    if (lane == 0) entbuf[warp] = ent;
    __syncthreads();
    if (tx == 0) {
        float t = 0.f;
        for (int w = 0; w < 8; w++) t += entbuf[w];
        atomicAdd(&d_ent, (double)t);
    }
}

// warp per row r: adjS[r] = sum_{m in csr[r]} S[m]  AND  E += dot(S[r], adjS[r])
__global__ void k_adjS_E(const float* __restrict__ S, float* __restrict__ adjS) {
    __shared__ float esm[8];
    int warp_l = threadIdx.x >> 5;
    int warp = (blockIdx.x * blockDim.x + threadIdx.x) >> 5;
    int lane = threadIdx.x & 31;
    float loc = 0.f;
    if (warp < BN) {
        int c = d_csr_cnt[warp];
        int cl = c < CAP ? c : CAP;
        const int* ip = d_csr_idx + warp * CAP;
        float4 acc = make_float4(0.f, 0.f, 0.f, 0.f);
        int e = 0;
        for (; e + 2 <= cl; e += 2) {
            int s0 = ip[e], s1 = ip[e + 1];
            float4 v0 = *(const float4*)(S + (size_t)s0 * Dt + (lane << 2));
            float4 v1 = *(const float4*)(S + (size_t)s1 * Dt + (lane << 2));
            acc.x += v0.x + v1.x; acc.y += v0.y + v1.y;
            acc.z += v0.z + v1.z; acc.w += v0.w + v1.w;
        }
        if (e < cl) {
            int s = ip[e];
            float4 v = *(const float4*)(S + (size_t)s * Dt + (lane << 2));
            acc.x += v.x; acc.y += v.y; acc.z += v.z; acc.w += v.w;
        }
        *(float4*)(adjS + (size_t)warp * Dt + (lane << 2)) = acc;
        float4 sr = *(const float4*)(S + (size_t)warp * Dt + (lane << 2));
        loc = sr.x * acc.x + sr.y * acc.y + sr.z * acc.z + sr.w * acc.w;
#pragma unroll
        for (int off = 16; off; off >>= 1) loc += __shfl_xor_sync(~0u, loc, off);
    }
    if (lane == 0) esm[warp_l] = loc;
    __syncthreads();
    if (threadIdx.x == 0) {
        float t = 0.f;
        for (int w = 0; w < 8; w++) t += esm[w];
        atomicAdd(&d_E, (double)t);
    }
}

// three batched A^T@B products in one launch: z selects (A,B,C) operands.
#define AR 32
#define AI 4
__global__ void k_atb3(const float* __restrict__ S, const float* __restrict__ hemb,
                       const float* __restrict__ adjS, float* __restrict__ hP,
                       float* __restrict__ aP, float* __restrict__ StS) {
    __shared__ float As[AR][Dt];
    __shared__ float Bs[AR][Dt];
    int b = blockIdx.y;
    int z = blockIdx.z;
    const float* A  = S;
    const float* Bm = (z == 0) ? hemb : (z == 1) ? adjS : S;
    float* C        = (z == 0) ? hP   : (z == 1) ? aP   : StS;
    ull acc[8][4];
#pragma unroll
    for (int i = 0; i < 8; i++)
#pragma unroll
        for (int j = 0; j < 4; j++) acc[i][j] = 0ull;
    int tk = threadIdx.x >> 4, td = threadIdx.x & 15;
    for (int c = 0; c < AI; c++) {
        int n0 = (blockIdx.x * AI + c) * AR;
        const float* Ap = A  + ((size_t)b * Nt + n0) * Dt;
        const float* Bp = Bm + ((size_t)b * Nt + n0) * Dt;
        __syncthreads();
        for (int t = threadIdx.x; t < AR * 32; t += 256) {
            int r = t >> 5, k4 = (t & 31) << 2;
            *(float4*)&As[r][k4] = *(const float4*)(Ap + r * Dt + k4);
            *(float4*)&Bs[r][k4] = *(const float4*)(Bp + r * Dt + k4);
        }
        __syncthreads();
        for (int n = 0; n < AR; n++) {
            float a[8];
            *(float4*)&a[0] = *(const float4*)&As[n][tk * 8];
            *(float4*)&a[4] = *(const float4*)&As[n][tk * 8 + 4];
            const ulonglong2* bp = (const ulonglong2*)&Bs[n][td * 8];
            ulonglong2 b01 = bp[0];
            ulonglong2 b23 = bp[1];
            ull ad[8];
#pragma unroll
            for (int i = 0; i < 8; i++) {
                unsigned int ab = __float_as_uint(a[i]);
                asm("mov.b64 %0, {%1, %1};" : "=l"(ad[i]) : "r"(ab));
            }
#pragma unroll
            for (int i = 0; i < 8; i++) {
                asm("fma.rn.f32x2 %0, %1, %2, %0;" : "+l"(acc[i][0]) : "l"(ad[i]), "l"(b01.x));
                asm("fma.rn.f32x2 %0, %1, %2, %0;" : "+l"(acc[i][1]) : "l"(ad[i]), "l"(b01.y));
                asm("fma.rn.f32x2 %0, %1, %2, %0;" : "+l"(acc[i][2]) : "l"(ad[i]), "l"(b23.x));
                asm("fma.rn.f32x2 %0, %1, %2, %0;" : "+l"(acc[i][3]) : "l"(ad[i]), "l"(b23.y));
            }
        }
    }
    size_t cb = (size_t)b * Dt * Dt;
#pragma unroll
    for (int i = 0; i < 8; i++)
#pragma unroll
        for (int j = 0; j < 4; j++) {
            float lo, hi;
            asm("mov.b64 {%0, %1}, %2;" : "=f"(lo), "=f"(hi) : "l"(acc[i][j]));
            atomicAdd(&C[cb + (size_t)(tk * 8 + i) * Dt + (td * 8 + 2 * j)], lo);
            atomicAdd(&C[cb + (size_t)(tk * 8 + i) * Dt + (td * 8 + 2 * j + 1)], hi);
        }
}

__global__ void k_sumcnt() {
    __shared__ float sm[8];
    int i = blockIdx.x * blockDim.x + threadIdx.x;
    float v = (i < BN) ? (float)d_csr_cnt[i] : 0.f;
#pragma unroll
    for (int off = 16; off; off >>= 1) v += __shfl_xor_sync(~0u, v, off);
    int wid = threadIdx.x >> 5, lane = threadIdx.x & 31;
    if (lane == 0) sm[wid] = v;
    __syncthreads();
    if (threadIdx.x == 0) {
        float t = 0.f;
        for (int w = 0; w < 8; w++) t += sm[w];
        atomicAdd(&d_nnz, (double)t);
    }
}

__global__ void k_sumsq() {
    __shared__ float sm[8];
    int i = blockIdx.x * blockDim.x + threadIdx.x;
    float x = (i < Bt * Dt * Dt) ? d_StS[i] : 0.f;
    float v = x * x;
#pragma unroll
    for (int off = 16; off; off >>= 1) v += __shfl_xor_sync(~0u, v, off);
    int wid = threadIdx.x >> 5, lane = threadIdx.x & 31;
    if (lane == 0) sm[wid] = v;
    __syncthreads();
    if (threadIdx.x == 0) {
        float t = 0.f;
        for (int w = 0; w < 8; w++) t += sm[w];
        atomicAdd(&d_F, (double)t);
    }
}

__global__ void k_final(float* out) {
    double l2 = d_nnz - 2.0 * d_E + d_F;
    if (l2 < 0.0) l2 = 0.0;
    out[2 * Bt * Dt * Dt]     = (float)(sqrt(l2) / ((double)Bt * Nt * Nt));
    out[2 * Bt * Dt * Dt + 1] = (float)(d_ent / (double)BN);
}

// ---------------- launch ----------------

extern "C" void kernel_launch(void* const* d_in, const int* in_sizes, int n_in,
                              void* d_out, int out_size) {
    const float* x    = (const float*)d_in[0];
    const float* adj  = (const float*)d_in[1];
    const float* We1l = (const float*)d_in[2];
    const float* be1  = (const float*)d_in[3];
    const float* We1r = (const float*)d_in[4];
    const float* We2l = (const float*)d_in[5];
    const float* be2  = (const float*)d_in[6];
    const float* We2r = (const float*)d_in[7];
    const float* Wa1l = (const float*)d_in[8];
    const float* ba1  = (const float*)d_in[9];
    const float* Wa1r = (const float*)d_in[10];
    const float* Wa2l = (const float*)d_in[11];
    const float* ba2  = (const float*)d_in[12];
    const float* Wa2r = (const float*)d_in[13];
    float* out = (float*)d_out;

    void* p;
    cudaGetSymbolAddress(&p, d_h1);    float* h1    = (float*)p;
    cudaGetSymbolAddress(&p, d_a1);    float* a1    = (float*)p;
    cudaGetSymbolAddress(&p, d_hemb);  float* hemb  = (float*)p;
    cudaGetSymbolAddress(&p, d_S);     float* S     = (float*)p;
    cudaGetSymbolAddress(&p, d_adjS);  float* adjS  = (float*)p;
    cudaGetSymbolAddress(&p, d_StS);   float* StS   = (float*)p;
    cudaGetSymbolAddress(&p, d_x2);    uint2* x2    = (uint2*)p;
    cudaGetSymbolAddress(&p, d_agg2);  uint2* agg2  = (uint2*)p;
    cudaGetSymbolAddress(&p, d_agg2a); uint2* agg2a = (uint2*)p;
    cudaGetSymbolAddress(&p, d_h1s);   uint2* h1s   = (uint2*)p;
    cudaGetSymbolAddress(&p, d_a1s);   uint2* a1s   = (uint2*)p;
    cudaGetSymbolAddress(&p, d_Ws);    uint2* Ws    = (uint2*)p;
    const int WSZ = 2 * Dt * DP2;

    k_clear<<<256, 256>>>(out, out_size);

    // CSR/CSC build + all bf16 splits, grid-packed into ONE launch
    k_build_split<<<BN + 2048 + 128, 256>>>(adj, x, x2,
                                            We1l, We1r, Wa1l, Wa1r,
                                            We2l, We2r, Wa2l, Wa2r);

    // agg1 = adj^T x / deg  (shared by emb1 and assign1), split form
    k_spmm<<<BN / 8, 256>>>(x, nullptr, agg2, 0, 1);

    // layer-1: both linears grid-packed into one launch
    k_linear_pair<<<dim3(BN / 64, 2), 256>>>(
        agg2, x2, Ws + 0 * WSZ, be1, h1, h1s,
        agg2, x2, Ws + 1 * WSZ, ba1, a1, a1s, -1);

    // layer-2 gathers fused (shared CSC index reads)
    k_spmm_dual<<<BN / 8, 256>>>(h1, a1, agg2, agg2a);

    // layer-2: both linears grid-packed; y=1 (assign) fuses softmax+entropy
    k_linear_pair<<<dim3(BN / 64, 2), 256>>>(
        agg2,  h1s, Ws + 2 * WSZ, be2, hemb, nullptr,
        agg2a, a1s, Ws + 3 * WSZ, ba2, S, nullptr, 1);

    // adjS = adj @ S (CSR gather) fused with E = sum_n dot(S[n], adjS[n])
    k_adjS_E<<<BN / 8, 256>>>(S, adjS);

    // three pooled products in ONE launch (384 blocks, fills the chip)
    k_atb3<<<dim3(Nt / (AR * AI), Bt, 3), 256>>>(S, hemb, adjS, out, out + Bt * Dt * Dt, StS);

    k_sumcnt<<<BN / 256, 256>>>();
    k_sumsq<<<(Bt * Dt * Dt) / 256, 256>>>();
    k_final<<<1, 1>>>(out);
}